// round 1
// baseline (speedup 1.0000x reference)
#include <cuda_runtime.h>
#include <math.h>

// ---------------------------------------------------------------------------
// GAT 2-layer forward:
//   L1: xp1 = x@W1 [N,2,64]; edge softmax (leakyrelu 0.2) over dst; agg; +b1; ELU
//   L2: xp2 = h@W2 [N,2,32]; edge softmax; agg; +b2; log_softmax over 64 ch
// Edges: 800k given + 50k self loops (appended).
// ---------------------------------------------------------------------------

#define NN 50000
#define EE 800000
#define ET (EE + NN)

// -------- scratch (device globals; no allocation allowed) -----------------
__device__ float    g_xp1 [NN * 128];
__device__ float    g_agg1[NN * 128];
__device__ float    g_xp2 [NN * 64];
__device__ float    g_agg2[NN * 64];
__device__ float    g_as  [NN * 2];
__device__ float    g_ad  [NN * 2];
__device__ float    g_e   [(long long)ET * 2];
__device__ unsigned g_emax[NN * 2];
__device__ float    g_den [NN * 2];
__device__ int      g_is32;

// -------- helpers -----------------------------------------------------------
__device__ __forceinline__ unsigned fkey(float f) {
    unsigned u = __float_as_uint(f);
    return (u & 0x80000000u) ? ~u : (u | 0x80000000u);
}
__device__ __forceinline__ float funkey(unsigned k) {
    unsigned u = (k & 0x80000000u) ? (k & 0x7fffffffu) : ~k;
    return __uint_as_float(u);
}

__device__ __forceinline__ void load_edge(const void* ei, long long E, long long e,
                                          int& s, int& d) {
    if (e >= E) { s = d = (int)(e - E); return; }  // self loop
    if (g_is32) {
        const int* p = (const int*)ei;
        s = p[e]; d = p[E + e];
    } else {
        const long long* p = (const long long*)ei;
        s = (int)p[e]; d = (int)p[E + e];
    }
}

// -------- init / detect -----------------------------------------------------
__global__ void initA_k(int n) {
    long long i = blockIdx.x * (long long)blockDim.x + threadIdx.x;
    if (i == 0) g_is32 = 0;
    if (i < (long long)n * 2) { g_emax[i] = 0u; g_den[i] = 0.f; }
    if (i < (long long)n * 128) g_agg1[i] = 0.f;
}
__global__ void initB_k(int n) {
    long long i = blockIdx.x * (long long)blockDim.x + threadIdx.x;
    if (i < (long long)n * 2) { g_emax[i] = 0u; g_den[i] = 0.f; }
    if (i < (long long)n * 64) g_agg2[i] = 0.f;
}
// int32 layout => odd 32-bit words are real node ids (almost surely nonzero);
// int64 layout => odd words are high halves of values < 2^31 => all zero.
__global__ void detect_k(const unsigned* w) {
    int i = blockIdx.x * blockDim.x + threadIdx.x;
    if (i < 4096 && w[2 * i + 1] != 0u) g_is32 = 1;
}

// -------- tiled SGEMM: Y[n,C] = X[n,K] @ W[K,C] -----------------------------
template <int K, int C, int KT, int R>
__global__ void gemm_k(const float* __restrict__ X, const float* __restrict__ W,
                       float* __restrict__ Y, int n) {
    __shared__ float Ws[KT * C];
    __shared__ float Xs[R * KT];
    const int c  = threadIdx.x;       // blockDim.x == C
    const int r0 = blockIdx.x * R;
    float acc[R];
#pragma unroll
    for (int r = 0; r < R; r++) acc[r] = 0.f;

    for (int kt = 0; kt < K; kt += KT) {
        __syncthreads();
        for (int i = c; i < KT * C; i += C)
            Ws[i] = W[(long long)(kt + i / C) * C + c];
        for (int i = c; i < R * KT; i += C) {
            int rr = i / KT, kk = i - rr * KT;
            int row = r0 + rr;
            Xs[i] = (row < n) ? X[(long long)row * K + kt + kk] : 0.f;
        }
        __syncthreads();
#pragma unroll
        for (int r = 0; r < R; r++) {
            float a = 0.f;
#pragma unroll
            for (int k = 0; k < KT; k++)
                a = fmaf(Xs[r * KT + k], Ws[k * C + c], a);
            acc[r] += a;
        }
    }
#pragma unroll
    for (int r = 0; r < R; r++)
        if (r0 + r < n) Y[(long long)(r0 + r) * C + c] = acc[r];
}

// -------- per-node attention dots: a_s[n,h], a_d[n,h] -----------------------
template <int C>
__global__ void attn_k(const float* __restrict__ xp, const float* __restrict__ as_,
                       const float* __restrict__ ad_, int n) {
    int g = blockIdx.x * blockDim.x + threadIdx.x;
    int w = g >> 5, lane = g & 31;
    int node = w >> 1, h = w & 1;
    if (node >= n) return;
    float ss = 0.f, dd = 0.f;
#pragma unroll
    for (int c = lane; c < C; c += 32) {
        float v = xp[(long long)(node * 2 + h) * C + c];
        ss += v * as_[h * C + c];
        dd += v * ad_[h * C + c];
    }
#pragma unroll
    for (int o = 16; o; o >>= 1) {
        ss += __shfl_xor_sync(0xffffffffu, ss, o);
        dd += __shfl_xor_sync(0xffffffffu, dd, o);
    }
    if (!lane) { g_as[node * 2 + h] = ss; g_ad[node * 2 + h] = dd; }
}

// -------- edge pass 1: e = leakyrelu(a_s[src]+a_d[dst]); segment max --------
__global__ void edge_max_k(const void* ei, long long E, int n) {
    long long e = blockIdx.x * (long long)blockDim.x + threadIdx.x;
    if (e >= E + n) return;
    int s, d;
    load_edge(ei, E, e, s, d);
#pragma unroll
    for (int h = 0; h < 2; h++) {
        float v = g_as[s * 2 + h] + g_ad[d * 2 + h];
        v = v > 0.f ? v : 0.2f * v;
        g_e[e * 2 + h] = v;
        atomicMax(&g_emax[d * 2 + h], fkey(v));
    }
}

// -------- edge pass 2: ee = exp(e - max); segment sum -----------------------
__global__ void edge_exps_k(const void* ei, long long E, int n) {
    long long e = blockIdx.x * (long long)blockDim.x + threadIdx.x;
    if (e >= E + n) return;
    int s, d;
    load_edge(ei, E, e, s, d);
#pragma unroll
    for (int h = 0; h < 2; h++) {
        float m  = funkey(g_emax[d * 2 + h]);
        float ee = expf(g_e[e * 2 + h] - m);
        g_e[e * 2 + h] = ee;
        atomicAdd(&g_den[d * 2 + h], ee);
    }
}

// -------- edge pass 3: agg[dst] += xp[src] * alpha  (warp per edge) ---------
template <int CH, int SH>
__global__ void edge_agg_k(const void* ei, const float* __restrict__ xp,
                           float* __restrict__ agg, long long E, int n) {
    long long t = blockIdx.x * (long long)blockDim.x + threadIdx.x;
    long long e = t >> 5;
    int lane = (int)(t & 31);
    if (e >= E + n) return;
    int s, d;
    load_edge(ei, E, e, s, d);
    float a0 = g_e[e * 2 + 0] / g_den[d * 2 + 0];
    float a1 = g_e[e * 2 + 1] / g_den[d * 2 + 1];
#pragma unroll
    for (int c = lane; c < CH; c += 32) {
        float al = (c >> SH) ? a1 : a0;
        atomicAdd(&agg[(long long)d * CH + c], xp[(long long)s * CH + c] * al);
    }
}

// -------- ELU(+bias) in place (layer 1, CH=128) -----------------------------
__global__ void elu_k(float* a, const float* __restrict__ b, long long total) {
    long long i = blockIdx.x * (long long)blockDim.x + threadIdx.x;
    if (i >= total) return;
    float v = a[i] + b[i & 127];
    a[i] = v > 0.f ? v : expm1f(v);
}

// -------- final: out = log_softmax(agg2 + b2), warp per node ----------------
__global__ void final_k(const float* __restrict__ agg, const float* __restrict__ b,
                        float* __restrict__ out, int n) {
    int g = blockIdx.x * blockDim.x + threadIdx.x;
    int node = g >> 5, lane = g & 31;
    if (node >= n) return;
    float v0 = agg[(long long)node * 64 + lane]      + b[lane];
    float v1 = agg[(long long)node * 64 + 32 + lane] + b[32 + lane];
    float m = fmaxf(v0, v1);
#pragma unroll
    for (int o = 16; o; o >>= 1) m = fmaxf(m, __shfl_xor_sync(0xffffffffu, m, o));
    float s = expf(v0 - m) + expf(v1 - m);
#pragma unroll
    for (int o = 16; o; o >>= 1) s += __shfl_xor_sync(0xffffffffu, s, o);
    float lse = m + logf(s);
    out[(long long)node * 64 + lane]      = v0 - lse;
    out[(long long)node * 64 + 32 + lane] = v1 - lse;
}

// ---------------------------------------------------------------------------
extern "C" void kernel_launch(void* const* d_in, const int* in_sizes, int n_in,
                              void* d_out, int out_size) {
    const float* x   = (const float*)d_in[0];
    const void*  ei  = d_in[1];
    const float* W1  = (const float*)d_in[2];
    const float* a1s = (const float*)d_in[3];
    const float* a1d = (const float*)d_in[4];
    const float* b1  = (const float*)d_in[5];
    const float* W2  = (const float*)d_in[6];
    const float* a2s = (const float*)d_in[7];
    const float* a2d = (const float*)d_in[8];
    const float* b2  = (const float*)d_in[9];
    float* out = (float*)d_out;

    const int       n  = in_sizes[0] / 128;            // 50000
    const long long E  = (long long)in_sizes[1] / 2;   // 800000
    const long long Et = E + n;

    float *xp1, *agg1, *xp2, *agg2;
    cudaGetSymbolAddress((void**)&xp1,  g_xp1);
    cudaGetSymbolAddress((void**)&agg1, g_agg1);
    cudaGetSymbolAddress((void**)&xp2,  g_xp2);
    cudaGetSymbolAddress((void**)&agg2, g_agg2);

    const int B = 256;
    // ---- layer 1 ----
    initA_k<<<(int)(((long long)n * 128 + B - 1) / B), B>>>(n);
    detect_k<<<(4096 + B - 1) / B, B>>>((const unsigned*)ei);
    gemm_k<128, 128, 64, 16><<<(n + 15) / 16, 128>>>(x, W1, xp1, n);
    attn_k<64><<<(int)(((long long)n * 64 + B - 1) / B), B>>>(xp1, a1s, a1d, n);
    edge_max_k <<<(int)((Et + B - 1) / B), B>>>(ei, E, n);
    edge_exps_k<<<(int)((Et + B - 1) / B), B>>>(ei, E, n);
    edge_agg_k<128, 6><<<(int)((Et * 32 + B - 1) / B), B>>>(ei, xp1, agg1, E, n);
    elu_k<<<(int)(((long long)n * 128 + B - 1) / B), B>>>(agg1, b1, (long long)n * 128);
    // ---- layer 2 ----
    gemm_k<128, 64, 64, 16><<<(n + 15) / 16, 64>>>(agg1, W2, xp2, n);
    attn_k<32><<<(int)(((long long)n * 64 + B - 1) / B), B>>>(xp2, a2s, a2d, n);
    initB_k<<<(int)(((long long)n * 64 + B - 1) / B), B>>>(n);
    edge_max_k <<<(int)((Et + B - 1) / B), B>>>(ei, E, n);
    edge_exps_k<<<(int)((Et + B - 1) / B), B>>>(ei, E, n);
    edge_agg_k<64, 5><<<(int)((Et * 32 + B - 1) / B), B>>>(ei, xp2, agg2, E, n);
    final_k<<<(int)(((long long)n * 32 + B - 1) / B), B>>>(agg2, b2, out, n);
}

// round 2
// speedup vs baseline: 1.8014x; 1.8014x over previous
#include <cuda_runtime.h>
#include <math.h>

// ---------------------------------------------------------------------------
// 2-layer GAT forward, CSR-based (no output atomics).
//   build CSR (hist/scan/scatter)            -- once per launch
//   L1: xp1 = x@W1; attn dots; per-node softmax; per-node agg (+b1, ELU)
//   L2: xp2 = h@W2; attn dots; per-node softmax; per-node agg (+b2, log_softmax)
// Edges: E given + N self loops appended.
// ---------------------------------------------------------------------------

#define NN 50000
#define EE 800000
#define ET (EE + NN)

// -------- scratch (device globals; no allocation allowed) -------------------
__device__ float  g_xp1[NN * 128];
__device__ float  g_h  [NN * 128];
__device__ float  g_xp2[NN * 64];
__device__ float2 g_as [NN];          // per-node (head0, head1) src dot
__device__ float2 g_ad [NN];          // per-node (head0, head1) dst dot
__device__ float2 g_p  [ET];          // alpha numerators by CSR slot
__device__ float2 g_den[NN];
__device__ int    g_deg[NN];
__device__ int    g_row[NN];          // row start
__device__ int    g_cur[NN];          // scatter cursor
__device__ int    g_src[ET];          // src node id by CSR slot
__device__ int    g_is32;

// -------- edge decode --------------------------------------------------------
__device__ __forceinline__ void load_edge(const void* ei, int E, int e,
                                          int& s, int& d) {
    if (e >= E) { s = d = e - E; return; }            // self loop
    if (g_is32) {
        const int* p = (const int*)ei;
        s = p[e]; d = p[E + e];
    } else {
        const long long* p = (const long long*)ei;
        s = (int)p[e]; d = (int)p[E + e];
    }
}

// -------- CSR build ----------------------------------------------------------
__global__ void init_k(int n) {
    int i = blockIdx.x * blockDim.x + threadIdx.x;
    if (i == 0) g_is32 = 0;
    if (i < n) g_deg[i] = 0;
}
// int32 layout => odd 32-bit words are node ids (almost surely some nonzero);
// int64 layout => odd words are high halves of values < 2^31 => all zero.
__global__ void detect_k(const unsigned* w) {
    int i = blockIdx.x * blockDim.x + threadIdx.x;
    if (i < 4096 && w[2 * i + 1] != 0u) g_is32 = 1;
}
__global__ void hist_k(const void* ei, int E, int n) {
    int e = blockIdx.x * blockDim.x + threadIdx.x;
    if (e >= E + n) return;
    int s, d; load_edge(ei, E, e, s, d);
    atomicAdd(&g_deg[d], 1);
}
__global__ void scan_k(int n) {          // single block, 1024 threads
    __shared__ int sm[1024];
    int tid   = threadIdx.x;
    int chunk = (n + 1023) >> 10;
    int lo = tid * chunk, hi = min(lo + chunk, n);
    int s = 0;
    for (int i = lo; i < hi; i++) s += g_deg[i];
    sm[tid] = s;
    __syncthreads();
    for (int off = 1; off < 1024; off <<= 1) {
        int v = (tid >= off) ? sm[tid - off] : 0;
        __syncthreads();
        sm[tid] += v;
        __syncthreads();
    }
    int excl = tid ? sm[tid - 1] : 0;
    for (int i = lo; i < hi; i++) {
        g_row[i] = excl; g_cur[i] = excl;
        excl += g_deg[i];
    }
}
__global__ void scatter_k(const void* ei, int E, int n) {
    int e = blockIdx.x * blockDim.x + threadIdx.x;
    if (e >= E + n) return;
    int s, d; load_edge(ei, E, e, s, d);
    int pos = atomicAdd(&g_cur[d], 1);
    g_src[pos] = s;
}

// -------- register-tiled SGEMM: Y[n,C] = X[n,128] @ W[128,C] ----------------
template <int C, int BM>
__global__ void gemm_k(const float* __restrict__ X, const float* __restrict__ W,
                       float* __restrict__ Y, int n) {
    constexpr int K = 128, BK = 16, TM = 8, TN = 4;
    constexpr int TCOLS = C / TN;                 // 32 (C=128) or 16 (C=64)
    constexpr int NT    = (BM / TM) * TCOLS;      // 256
    __shared__ float Xs[BK][BM];
    __shared__ float Ws[BK][C];
    const int tid = threadIdx.x;
    const int tc = tid % TCOLS, tr = tid / TCOLS;
    const int row0 = blockIdx.x * BM;
    float acc[TM][TN];
#pragma unroll
    for (int i = 0; i < TM; i++)
#pragma unroll
        for (int j = 0; j < TN; j++) acc[i][j] = 0.f;

    for (int kt = 0; kt < K; kt += BK) {
#pragma unroll
        for (int idx = tid; idx < BM * BK / 4; idx += NT) {
            int m = idx / (BK / 4), q = idx % (BK / 4);
            float4 v = make_float4(0.f, 0.f, 0.f, 0.f);
            if (row0 + m < n)
                v = *(const float4*)&X[(long long)(row0 + m) * K + kt + q * 4];
            Xs[q * 4 + 0][m] = v.x; Xs[q * 4 + 1][m] = v.y;
            Xs[q * 4 + 2][m] = v.z; Xs[q * 4 + 3][m] = v.w;
        }
#pragma unroll
        for (int idx = tid; idx < BK * C / 4; idx += NT) {
            int k = idx / (C / 4), q = idx % (C / 4);
            *(float4*)&Ws[k][q * 4] = *(const float4*)&W[(kt + k) * C + q * 4];
        }
        __syncthreads();
#pragma unroll
        for (int k = 0; k < BK; k++) {
            float4 x0 = *(const float4*)&Xs[k][tr * TM];
            float4 x1 = *(const float4*)&Xs[k][tr * TM + 4];
            float4 w  = *(const float4*)&Ws[k][tc * TN];
            float xr[TM] = {x0.x, x0.y, x0.z, x0.w, x1.x, x1.y, x1.z, x1.w};
            float wr[TN] = {w.x, w.y, w.z, w.w};
#pragma unroll
            for (int i = 0; i < TM; i++)
#pragma unroll
                for (int j = 0; j < TN; j++) acc[i][j] = fmaf(xr[i], wr[j], acc[i][j]);
        }
        __syncthreads();
    }
#pragma unroll
    for (int i = 0; i < TM; i++) {
        int r = row0 + tr * TM + i;
        if (r < n)
            *(float4*)&Y[(long long)r * C + tc * TN] =
                make_float4(acc[i][0], acc[i][1], acc[i][2], acc[i][3]);
    }
}

// -------- attn dots: g_as[n]=(xp_h·att_src), g_ad likewise ------------------
template <int C>   // per-head width (64 or 32)
__global__ void attn_k(const float* __restrict__ xp, const float* __restrict__ as_,
                       const float* __restrict__ ad_, int n) {
    int g = blockIdx.x * blockDim.x + threadIdx.x;
    int node = g >> 5, lane = g & 31;
    if (node >= n) return;
    constexpr int F4   = 2 * C / 4;   // active float4 lanes (32 or 16)
    constexpr int HALF = F4 / 2;      // lanes per head (16 or 8)
    float ss = 0.f, dd = 0.f;
    if (lane < F4) {
        float4 v = ((const float4*)(xp + (long long)node * 2 * C))[lane];
        float4 a = ((const float4*)as_)[lane];
        float4 b = ((const float4*)ad_)[lane];
        ss = v.x * a.x + v.y * a.y + v.z * a.z + v.w * a.w;
        dd = v.x * b.x + v.y * b.y + v.z * b.z + v.w * b.w;
    }
#pragma unroll
    for (int o = HALF / 2; o; o >>= 1) {
        ss += __shfl_xor_sync(0xffffffffu, ss, o);
        dd += __shfl_xor_sync(0xffffffffu, dd, o);
    }
    if (lane < F4 && (lane & (HALF - 1)) == 0) {
        int h = lane / HALF;
        ((float*)g_as)[node * 2 + h] = ss;
        ((float*)g_ad)[node * 2 + h] = dd;
    }
}

// -------- per-node softmax numerators + denominators (warp/node) ------------
__global__ void alpha_k(int n) {
    int g = blockIdx.x * blockDim.x + threadIdx.x;
    int node = g >> 5, lane = g & 31;
    if (node >= n) return;
    int start = g_row[node], deg = g_deg[node];
    float2 ad = g_ad[node];
    float m0 = -1e30f, m1 = -1e30f;
    for (int i = lane; i < deg; i += 32) {
        int s = g_src[start + i];
        float2 as = g_as[s];
        float e0 = as.x + ad.x; e0 = e0 > 0.f ? e0 : 0.2f * e0;
        float e1 = as.y + ad.y; e1 = e1 > 0.f ? e1 : 0.2f * e1;
        m0 = fmaxf(m0, e0); m1 = fmaxf(m1, e1);
    }
#pragma unroll
    for (int o = 16; o; o >>= 1) {
        m0 = fmaxf(m0, __shfl_xor_sync(0xffffffffu, m0, o));
        m1 = fmaxf(m1, __shfl_xor_sync(0xffffffffu, m1, o));
    }
    float s0 = 0.f, s1 = 0.f;
    for (int i = lane; i < deg; i += 32) {
        int s = g_src[start + i];
        float2 as = g_as[s];
        float e0 = as.x + ad.x; e0 = e0 > 0.f ? e0 : 0.2f * e0;
        float e1 = as.y + ad.y; e1 = e1 > 0.f ? e1 : 0.2f * e1;
        float p0 = expf(e0 - m0), p1 = expf(e1 - m1);
        g_p[start + i] = make_float2(p0, p1);
        s0 += p0; s1 += p1;
    }
#pragma unroll
    for (int o = 16; o; o >>= 1) {
        s0 += __shfl_xor_sync(0xffffffffu, s0, o);
        s1 += __shfl_xor_sync(0xffffffffu, s1, o);
    }
    if (!lane) g_den[node] = make_float2(s0, s1);
}

// -------- layer-1 aggregation: h = ELU(sum alpha*xp1 + b1)  (warp/node) -----
__global__ void agg1_k(const float* __restrict__ xp, const float* __restrict__ b1,
                       float* __restrict__ h, int n) {
    int g = blockIdx.x * blockDim.x + threadIdx.x;
    int node = g >> 5, lane = g & 31;
    if (node >= n) return;
    int start = g_row[node], deg = g_deg[node];
    float2 den = g_den[node];
    float r0 = 1.f / den.x, r1 = 1.f / den.y;
    float4 acc = make_float4(0.f, 0.f, 0.f, 0.f);
    const float4* xp4 = (const float4*)xp;
    int base = 0;
    for (; base + 32 <= deg; base += 32) {
        int   s = g_src[start + base + lane];
        float2 p = g_p[start + base + lane];
        float a0 = p.x * r0, a1 = p.y * r1;
#pragma unroll 4
        for (int j = 0; j < 32; j++) {
            int   ss = __shfl_sync(0xffffffffu, s,  j);
            float f0 = __shfl_sync(0xffffffffu, a0, j);
            float f1 = __shfl_sync(0xffffffffu, a1, j);
            float a  = lane < 16 ? f0 : f1;
            float4 v = xp4[(long long)ss * 32 + lane];
            acc.x = fmaf(v.x, a, acc.x); acc.y = fmaf(v.y, a, acc.y);
            acc.z = fmaf(v.z, a, acc.z); acc.w = fmaf(v.w, a, acc.w);
        }
    }
    int rem = deg - base;
    if (rem) {
        int s = 0; float a0 = 0.f, a1 = 0.f;
        if (lane < rem) {
            s = g_src[start + base + lane];
            float2 p = g_p[start + base + lane];
            a0 = p.x * r0; a1 = p.y * r1;
        }
        for (int j = 0; j < rem; j++) {
            int   ss = __shfl_sync(0xffffffffu, s,  j);
            float f0 = __shfl_sync(0xffffffffu, a0, j);
            float f1 = __shfl_sync(0xffffffffu, a1, j);
            float a  = lane < 16 ? f0 : f1;
            float4 v = xp4[(long long)ss * 32 + lane];
            acc.x = fmaf(v.x, a, acc.x); acc.y = fmaf(v.y, a, acc.y);
            acc.z = fmaf(v.z, a, acc.z); acc.w = fmaf(v.w, a, acc.w);
        }
    }
    float4 bb = ((const float4*)b1)[lane];
    acc.x += bb.x; acc.y += bb.y; acc.z += bb.z; acc.w += bb.w;
    acc.x = acc.x > 0.f ? acc.x : expm1f(acc.x);
    acc.y = acc.y > 0.f ? acc.y : expm1f(acc.y);
    acc.z = acc.z > 0.f ? acc.z : expm1f(acc.z);
    acc.w = acc.w > 0.f ? acc.w : expm1f(acc.w);
    ((float4*)h)[(long long)node * 32 + lane] = acc;
}

// -------- layer-2 aggregation + bias + log_softmax  (warp/node) -------------
__global__ void agg2_k(const float* __restrict__ xp, const float* __restrict__ b2,
                       float* __restrict__ out, int n) {
    int g = blockIdx.x * blockDim.x + threadIdx.x;
    int node = g >> 5, lane = g & 31;
    if (node >= n) return;
    int start = g_row[node], deg = g_deg[node];
    float2 den = g_den[node];
    float r0 = 1.f / den.x, r1 = 1.f / den.y;
    float ax = 0.f, ay = 0.f;
    const float2* xp2 = (const float2*)xp;
    int base = 0;
    for (; base + 32 <= deg; base += 32) {
        int   s = g_src[start + base + lane];
        float2 p = g_p[start + base + lane];
        float a0 = p.x * r0, a1 = p.y * r1;
#pragma unroll 4
        for (int j = 0; j < 32; j++) {
            int   ss = __shfl_sync(0xffffffffu, s,  j);
            float f0 = __shfl_sync(0xffffffffu, a0, j);
            float f1 = __shfl_sync(0xffffffffu, a1, j);
            float a  = lane < 16 ? f0 : f1;
            float2 v = xp2[(long long)ss * 32 + lane];
            ax = fmaf(v.x, a, ax); ay = fmaf(v.y, a, ay);
        }
    }
    int rem = deg - base;
    if (rem) {
        int s = 0; float a0 = 0.f, a1 = 0.f;
        if (lane < rem) {
            s = g_src[start + base + lane];
            float2 p = g_p[start + base + lane];
            a0 = p.x * r0; a1 = p.y * r1;
        }
        for (int j = 0; j < rem; j++) {
            int   ss = __shfl_sync(0xffffffffu, s,  j);
            float f0 = __shfl_sync(0xffffffffu, a0, j);
            float f1 = __shfl_sync(0xffffffffu, a1, j);
            float a  = lane < 16 ? f0 : f1;
            float2 v = xp2[(long long)ss * 32 + lane];
            ax = fmaf(v.x, a, ax); ay = fmaf(v.y, a, ay);
        }
    }
    float2 bb = ((const float2*)b2)[lane];
    float v0 = ax + bb.x, v1 = ay + bb.y;
    float m = fmaxf(v0, v1);
#pragma unroll
    for (int o = 16; o; o >>= 1) m = fmaxf(m, __shfl_xor_sync(0xffffffffu, m, o));
    float sm = expf(v0 - m) + expf(v1 - m);
#pragma unroll
    for (int o = 16; o; o >>= 1) sm += __shfl_xor_sync(0xffffffffu, sm, o);
    float lse = m + logf(sm);
    ((float2*)out)[(long long)node * 32 + lane] = make_float2(v0 - lse, v1 - lse);
}

// ---------------------------------------------------------------------------
extern "C" void kernel_launch(void* const* d_in, const int* in_sizes, int n_in,
                              void* d_out, int out_size) {
    const float* x   = (const float*)d_in[0];
    const void*  ei  = d_in[1];
    const float* W1  = (const float*)d_in[2];
    const float* a1s = (const float*)d_in[3];
    const float* a1d = (const float*)d_in[4];
    const float* b1  = (const float*)d_in[5];
    const float* W2  = (const float*)d_in[6];
    const float* a2s = (const float*)d_in[7];
    const float* a2d = (const float*)d_in[8];
    const float* b2  = (const float*)d_in[9];
    float* out = (float*)d_out;

    const int n  = in_sizes[0] / 128;          // 50000
    const int E  = in_sizes[1] / 2;            // 800000
    const int Et = E + n;

    float *xp1, *h, *xp2;
    cudaGetSymbolAddress((void**)&xp1, g_xp1);
    cudaGetSymbolAddress((void**)&h,   g_h);
    cudaGetSymbolAddress((void**)&xp2, g_xp2);

    const int B = 256;
    const int nwB = (n * 32 + B - 1) / B;      // warp-per-node grids

    // ---- CSR build (shared by both layers) ----
    init_k   <<<(n + B - 1) / B, B>>>(n);
    detect_k <<<(4096 + B - 1) / B, B>>>((const unsigned*)ei);
    hist_k   <<<(Et + B - 1) / B, B>>>(ei, E, n);
    scan_k   <<<1, 1024>>>(n);
    scatter_k<<<(Et + B - 1) / B, B>>>(ei, E, n);

    // ---- layer 1 ----
    gemm_k<128, 64><<<(n + 63) / 64, 256>>>(x, W1, xp1, n);
    attn_k<64><<<nwB, B>>>(xp1, a1s, a1d, n);
    alpha_k<<<nwB, B>>>(n);
    agg1_k<<<nwB, B>>>(xp1, b1, h, n);

    // ---- layer 2 ----
    gemm_k<64, 128><<<(n + 127) / 128, 256>>>(h, W2, xp2, n);
    attn_k<32><<<nwB, B>>>(xp2, a2s, a2d, n);
    alpha_k<<<nwB, B>>>(n);
    agg2_k<<<nwB, B>>>(xp2, b2, out, n);
}

// round 3
// speedup vs baseline: 2.5784x; 1.4314x over previous
#include <cuda_runtime.h>
#include <math.h>

// ---------------------------------------------------------------------------
// 2-layer GAT forward, CSR-based (no output atomics).
//   CSR: hist -> multi-block scan (3 kernels) -> scatter
//   L1: xp1 = x@W1; attn dots; fused softmax+agg (+b1, ELU)
//   L2: xp2 = h@W2; attn dots; fused softmax+agg (+b2, log_softmax)
// ---------------------------------------------------------------------------

#define NN 50000
#define EE 800000
#define ET (EE + NN)
#define NB ((NN + 1023) / 1024)   // scan blocks (49)

// -------- scratch (device globals; no allocation allowed) -------------------
__device__ float  g_xp1[NN * 128];
__device__ float  g_h  [NN * 128];
__device__ float  g_xp2[NN * 64];
__device__ float2 g_as [NN];          // per-node (head0, head1) src dot
__device__ float2 g_ad [NN];          // per-node (head0, head1) dst dot
__device__ int    g_deg[NN];
__device__ int    g_row[NN];          // row start
__device__ int    g_cur[NN];          // scatter cursor
__device__ int    g_src[ET];          // src node id by CSR slot
__device__ int    g_bsum[NB];
__device__ int    g_boff[NB];
__device__ int    g_is32;

// -------- edge decode --------------------------------------------------------
__device__ __forceinline__ void load_edge(const void* ei, int E, int e,
                                          int& s, int& d) {
    if (e >= E) { s = d = e - E; return; }            // self loop
    if (g_is32) {
        const int* p = (const int*)ei;
        s = p[e]; d = p[E + e];
    } else {
        const long long* p = (const long long*)ei;
        s = (int)p[e]; d = (int)p[E + e];
    }
}

// -------- CSR build ----------------------------------------------------------
__global__ void init_k(int n) {
    int i = blockIdx.x * blockDim.x + threadIdx.x;
    if (i == 0) g_is32 = 0;
    if (i < n) g_deg[i] = 0;
}
// int32 layout => odd 32-bit words are node ids (some nonzero);
// int64 layout => odd words are high halves of values < 2^31 => all zero.
__global__ void detect_k(const unsigned* w) {
    int i = blockIdx.x * blockDim.x + threadIdx.x;
    if (i < 4096 && w[2 * i + 1] != 0u) g_is32 = 1;
}
__global__ void hist_k(const void* ei, int E, int n) {
    int e = blockIdx.x * blockDim.x + threadIdx.x;
    if (e >= E + n) return;
    int s, d; load_edge(ei, E, e, s, d);
    atomicAdd(&g_deg[d], 1);
}

// ---- device-wide exclusive scan of g_deg -> g_row/g_cur (3 kernels) --------
__global__ void scan_bsum_k(int n) {          // grid NB, block 256, 4/thread
    __shared__ int wsum[8];
    int b = blockIdx.x, t = threadIdx.x;
    int base = b * 1024 + t * 4;
    int s = 0;
#pragma unroll
    for (int j = 0; j < 4; j++) {
        int i = base + j;
        if (i < n) s += g_deg[i];
    }
    int lane = t & 31, w = t >> 5;
#pragma unroll
    for (int o = 16; o; o >>= 1) s += __shfl_xor_sync(0xffffffffu, s, o);
    if (lane == 0) wsum[w] = s;
    __syncthreads();
    if (t == 0) {
        int tot = 0;
#pragma unroll
        for (int j = 0; j < 8; j++) tot += wsum[j];
        g_bsum[b] = tot;
    }
}
__global__ void scan_top_k(int nb) {          // single block, 64 threads
    __shared__ int w0tot;
    int t = threadIdx.x, lane = t & 31, w = t >> 5;
    int v = (t < nb) ? g_bsum[t] : 0;
    int inc = v;
#pragma unroll
    for (int o = 1; o < 32; o <<= 1) {
        int x = __shfl_up_sync(0xffffffffu, inc, o);
        if (lane >= o) inc += x;
    }
    if (w == 0 && lane == 31) w0tot = inc;
    __syncthreads();
    if (w == 1) inc += w0tot;
    if (t < nb) g_boff[t] = inc - v;
}
__global__ void scan_out_k(int n) {           // grid NB, block 256, 4/thread
    __shared__ int wsum[8], woff[8];
    int b = blockIdx.x, t = threadIdx.x;
    int lane = t & 31, w = t >> 5;
    int base = b * 1024 + t * 4;
    int v[4];
#pragma unroll
    for (int j = 0; j < 4; j++) {
        int i = base + j;
        v[j] = (i < n) ? g_deg[i] : 0;
    }
    int s = v[0] + v[1] + v[2] + v[3];
    int inc = s;
#pragma unroll
    for (int o = 1; o < 32; o <<= 1) {
        int x = __shfl_up_sync(0xffffffffu, inc, o);
        if (lane >= o) inc += x;
    }
    if (lane == 31) wsum[w] = inc;
    __syncthreads();
    if (w == 0) {
        int x = (lane < 8) ? wsum[lane] : 0;
        int i8 = x;
#pragma unroll
        for (int o = 1; o < 8; o <<= 1) {
            int y = __shfl_up_sync(0xffffffffu, i8, o);
            if (lane >= o) i8 += y;
        }
        if (lane < 8) woff[lane] = i8 - x;
    }
    __syncthreads();
    int off = g_boff[b] + woff[w] + (inc - s);
#pragma unroll
    for (int j = 0; j < 4; j++) {
        int i = base + j;
        if (i < n) { g_row[i] = off; g_cur[i] = off; }
        off += v[j];
    }
}

__global__ void scatter_k(const void* ei, int E, int n) {
    int e = blockIdx.x * blockDim.x + threadIdx.x;
    if (e >= E + n) return;
    int s, d; load_edge(ei, E, e, s, d);
    int pos = atomicAdd(&g_cur[d], 1);
    g_src[pos] = s;
}

// -------- register-tiled SGEMM: Y[n,C] = X[n,128] @ W[128,C] ----------------
template <int C, int BM>
__global__ void gemm_k(const float* __restrict__ X, const float* __restrict__ W,
                       float* __restrict__ Y, int n) {
    constexpr int K = 128, BK = 16, TM = 8, TN = 4;
    constexpr int TCOLS = C / TN;
    constexpr int NT    = (BM / TM) * TCOLS;      // 256
    __shared__ float Xs[BK][BM];
    __shared__ float Ws[BK][C];
    const int tid = threadIdx.x;
    const int tc = tid % TCOLS, tr = tid / TCOLS;
    const int row0 = blockIdx.x * BM;
    float acc[TM][TN];
#pragma unroll
    for (int i = 0; i < TM; i++)
#pragma unroll
        for (int j = 0; j < TN; j++) acc[i][j] = 0.f;

    for (int kt = 0; kt < K; kt += BK) {
#pragma unroll
        for (int idx = tid; idx < BM * BK / 4; idx += NT) {
            int m = idx / (BK / 4), q = idx % (BK / 4);
            float4 v = make_float4(0.f, 0.f, 0.f, 0.f);
            if (row0 + m < n)
                v = *(const float4*)&X[(long long)(row0 + m) * K + kt + q * 4];
            Xs[q * 4 + 0][m] = v.x; Xs[q * 4 + 1][m] = v.y;
            Xs[q * 4 + 2][m] = v.z; Xs[q * 4 + 3][m] = v.w;
        }
#pragma unroll
        for (int idx = tid; idx < BK * C / 4; idx += NT) {
            int k = idx / (C / 4), q = idx % (C / 4);
            *(float4*)&Ws[k][q * 4] = *(const float4*)&W[(kt + k) * C + q * 4];
        }
        __syncthreads();
#pragma unroll
        for (int k = 0; k < BK; k++) {
            float4 x0 = *(const float4*)&Xs[k][tr * TM];
            float4 x1 = *(const float4*)&Xs[k][tr * TM + 4];
            float4 w  = *(const float4*)&Ws[k][tc * TN];
            float xr[TM] = {x0.x, x0.y, x0.z, x0.w, x1.x, x1.y, x1.z, x1.w};
            float wr[TN] = {w.x, w.y, w.z, w.w};
#pragma unroll
            for (int i = 0; i < TM; i++)
#pragma unroll
                for (int j = 0; j < TN; j++) acc[i][j] = fmaf(xr[i], wr[j], acc[i][j]);
        }
        __syncthreads();
    }
#pragma unroll
    for (int i = 0; i < TM; i++) {
        int r = row0 + tr * TM + i;
        if (r < n)
            *(float4*)&Y[(long long)r * C + tc * TN] =
                make_float4(acc[i][0], acc[i][1], acc[i][2], acc[i][3]);
    }
}

// -------- attn dots ---------------------------------------------------------
template <int C>   // per-head width (64 or 32)
__global__ void attn_k(const float* __restrict__ xp, const float* __restrict__ as_,
                       const float* __restrict__ ad_, int n) {
    int g = blockIdx.x * blockDim.x + threadIdx.x;
    int node = g >> 5, lane = g & 31;
    if (node >= n) return;
    constexpr int F4   = 2 * C / 4;
    constexpr int HALF = F4 / 2;
    float ss = 0.f, dd = 0.f;
    if (lane < F4) {
        float4 v = ((const float4*)(xp + (long long)node * 2 * C))[lane];
        float4 a = ((const float4*)as_)[lane];
        float4 b = ((const float4*)ad_)[lane];
        ss = v.x * a.x + v.y * a.y + v.z * a.z + v.w * a.w;
        dd = v.x * b.x + v.y * b.y + v.z * b.z + v.w * b.w;
    }
#pragma unroll
    for (int o = HALF / 2; o; o >>= 1) {
        ss += __shfl_xor_sync(0xffffffffu, ss, o);
        dd += __shfl_xor_sync(0xffffffffu, dd, o);
    }
    if (lane < F4 && (lane & (HALF - 1)) == 0) {
        int h = lane / HALF;
        ((float*)g_as)[node * 2 + h] = ss;
        ((float*)g_ad)[node * 2 + h] = dd;
    }
}

// -------- fused softmax+agg, layer 1: h = ELU((sum p*xp)/den + b1) ----------
__global__ void agg1_k(const float* __restrict__ xp, const float* __restrict__ b1,
                       float* __restrict__ h, int n) {
    int g = blockIdx.x * blockDim.x + threadIdx.x;
    int node = g >> 5, lane = g & 31;
    if (node >= n) return;
    int start = g_row[node], deg = g_deg[node];
    float2 ad = g_ad[node];
    // pass 1: segment max
    float m0 = -1e30f, m1 = -1e30f;
    for (int i = lane; i < deg; i += 32) {
        float2 as = g_as[g_src[start + i]];
        float e0 = as.x + ad.x; e0 = e0 > 0.f ? e0 : 0.2f * e0;
        float e1 = as.y + ad.y; e1 = e1 > 0.f ? e1 : 0.2f * e1;
        m0 = fmaxf(m0, e0); m1 = fmaxf(m1, e1);
    }
#pragma unroll
    for (int o = 16; o; o >>= 1) {
        m0 = fmaxf(m0, __shfl_xor_sync(0xffffffffu, m0, o));
        m1 = fmaxf(m1, __shfl_xor_sync(0xffffffffu, m1, o));
    }
    // pass 2: p = exp(e-m); den += p; acc += p * xp[src]
    float4 acc = make_float4(0.f, 0.f, 0.f, 0.f);
    float d0 = 0.f, d1 = 0.f;
    const float4* xp4 = (const float4*)xp;
    int base = 0;
    for (; base + 32 <= deg; base += 32) {
        int s = g_src[start + base + lane];
        float2 as = g_as[s];
        float e0 = as.x + ad.x; e0 = e0 > 0.f ? e0 : 0.2f * e0;
        float e1 = as.y + ad.y; e1 = e1 > 0.f ? e1 : 0.2f * e1;
        float p0 = expf(e0 - m0), p1 = expf(e1 - m1);
        d0 += p0; d1 += p1;
#pragma unroll 4
        for (int j = 0; j < 32; j++) {
            int   ss = __shfl_sync(0xffffffffu, s,  j);
            float f0 = __shfl_sync(0xffffffffu, p0, j);
            float f1 = __shfl_sync(0xffffffffu, p1, j);
            float a  = lane < 16 ? f0 : f1;
            float4 v = xp4[(long long)ss * 32 + lane];
            acc.x = fmaf(v.x, a, acc.x); acc.y = fmaf(v.y, a, acc.y);
            acc.z = fmaf(v.z, a, acc.z); acc.w = fmaf(v.w, a, acc.w);
        }
    }
    int rem = deg - base;
    if (rem) {
        int s = 0; float p0 = 0.f, p1 = 0.f;
        if (lane < rem) {
            s = g_src[start + base + lane];
            float2 as = g_as[s];
            float e0 = as.x + ad.x; e0 = e0 > 0.f ? e0 : 0.2f * e0;
            float e1 = as.y + ad.y; e1 = e1 > 0.f ? e1 : 0.2f * e1;
            p0 = expf(e0 - m0); p1 = expf(e1 - m1);
        }
        d0 += p0; d1 += p1;
        for (int j = 0; j < rem; j++) {
            int   ss = __shfl_sync(0xffffffffu, s,  j);
            float f0 = __shfl_sync(0xffffffffu, p0, j);
            float f1 = __shfl_sync(0xffffffffu, p1, j);
            float a  = lane < 16 ? f0 : f1;
            float4 v = xp4[(long long)ss * 32 + lane];
            acc.x = fmaf(v.x, a, acc.x); acc.y = fmaf(v.y, a, acc.y);
            acc.z = fmaf(v.z, a, acc.z); acc.w = fmaf(v.w, a, acc.w);
        }
    }
#pragma unroll
    for (int o = 16; o; o >>= 1) {
        d0 += __shfl_xor_sync(0xffffffffu, d0, o);
        d1 += __shfl_xor_sync(0xffffffffu, d1, o);
    }
    float r = 1.f / (lane < 16 ? d0 : d1);
    float4 bb = ((const float4*)b1)[lane];
    acc.x = fmaf(acc.x, r, bb.x); acc.y = fmaf(acc.y, r, bb.y);
    acc.z = fmaf(acc.z, r, bb.z); acc.w = fmaf(acc.w, r, bb.w);
    acc.x = acc.x > 0.f ? acc.x : expm1f(acc.x);
    acc.y = acc.y > 0.f ? acc.y : expm1f(acc.y);
    acc.z = acc.z > 0.f ? acc.z : expm1f(acc.z);
    acc.w = acc.w > 0.f ? acc.w : expm1f(acc.w);
    ((float4*)h)[(long long)node * 32 + lane] = acc;
}

// -------- fused softmax+agg, layer 2 (+bias, log_softmax) -------------------
__global__ void agg2_k(const float* __restrict__ xp, const float* __restrict__ b2,
                       float* __restrict__ out, int n) {
    int g = blockIdx.x * blockDim.x + threadIdx.x;
    int node = g >> 5, lane = g & 31;
    if (node >= n) return;
    int start = g_row[node], deg = g_deg[node];
    float2 ad = g_ad[node];
    float m0 = -1e30f, m1 = -1e30f;
    for (int i = lane; i < deg; i += 32) {
        float2 as = g_as[g_src[start + i]];
        float e0 = as.x + ad.x; e0 = e0 > 0.f ? e0 : 0.2f * e0;
        float e1 = as.y + ad.y; e1 = e1 > 0.f ? e1 : 0.2f * e1;
        m0 = fmaxf(m0, e0); m1 = fmaxf(m1, e1);
    }
#pragma unroll
    for (int o = 16; o; o >>= 1) {
        m0 = fmaxf(m0, __shfl_xor_sync(0xffffffffu, m0, o));
        m1 = fmaxf(m1, __shfl_xor_sync(0xffffffffu, m1, o));
    }
    float ax = 0.f, ay = 0.f, d0 = 0.f, d1 = 0.f;
    const float2* xp2 = (const float2*)xp;
    int base = 0;
    for (; base + 32 <= deg; base += 32) {
        int s = g_src[start + base + lane];
        float2 as = g_as[s];
        float e0 = as.x + ad.x; e0 = e0 > 0.f ? e0 : 0.2f * e0;
        float e1 = as.y + ad.y; e1 = e1 > 0.f ? e1 : 0.2f * e1;
        float p0 = expf(e0 - m0), p1 = expf(e1 - m1);
        d0 += p0; d1 += p1;
#pragma unroll 4
        for (int j = 0; j < 32; j++) {
            int   ss = __shfl_sync(0xffffffffu, s,  j);
            float f0 = __shfl_sync(0xffffffffu, p0, j);
            float f1 = __shfl_sync(0xffffffffu, p1, j);
            float a  = lane < 16 ? f0 : f1;
            float2 v = xp2[(long long)ss * 32 + lane];
            ax = fmaf(v.x, a, ax); ay = fmaf(v.y, a, ay);
        }
    }
    int rem = deg - base;
    if (rem) {
        int s = 0; float p0 = 0.f, p1 = 0.f;
        if (lane < rem) {
            s = g_src[start + base + lane];
            float2 as = g_as[s];
            float e0 = as.x + ad.x; e0 = e0 > 0.f ? e0 : 0.2f * e0;
            float e1 = as.y + ad.y; e1 = e1 > 0.f ? e1 : 0.2f * e1;
            p0 = expf(e0 - m0); p1 = expf(e1 - m1);
        }
        d0 += p0; d1 += p1;
        for (int j = 0; j < rem; j++) {
            int   ss = __shfl_sync(0xffffffffu, s,  j);
            float f0 = __shfl_sync(0xffffffffu, p0, j);
            float f1 = __shfl_sync(0xffffffffu, p1, j);
            float a  = lane < 16 ? f0 : f1;
            float2 v = xp2[(long long)ss * 32 + lane];
            ax = fmaf(v.x, a, ax); ay = fmaf(v.y, a, ay);
        }
    }
#pragma unroll
    for (int o = 16; o; o >>= 1) {
        d0 += __shfl_xor_sync(0xffffffffu, d0, o);
        d1 += __shfl_xor_sync(0xffffffffu, d1, o);
    }
    float r = 1.f / (lane < 16 ? d0 : d1);
    float2 bb = ((const float2*)b2)[lane];
    float v0 = fmaf(ax, r, bb.x), v1 = fmaf(ay, r, bb.y);
    float m = fmaxf(v0, v1);
#pragma unroll
    for (int o = 16; o; o >>= 1) m = fmaxf(m, __shfl_xor_sync(0xffffffffu, m, o));
    float sm = expf(v0 - m) + expf(v1 - m);
#pragma unroll
    for (int o = 16; o; o >>= 1) sm += __shfl_xor_sync(0xffffffffu, sm, o);
    float lse = m + logf(sm);
    ((float2*)out)[(long long)node * 32 + lane] = make_float2(v0 - lse, v1 - lse);
}

// ---------------------------------------------------------------------------
extern "C" void kernel_launch(void* const* d_in, const int* in_sizes, int n_in,
                              void* d_out, int out_size) {
    const float* x   = (const float*)d_in[0];
    const void*  ei  = d_in[1];
    const float* W1  = (const float*)d_in[2];
    const float* a1s = (const float*)d_in[3];
    const float* a1d = (const float*)d_in[4];
    const float* b1  = (const float*)d_in[5];
    const float* W2  = (const float*)d_in[6];
    const float* a2s = (const float*)d_in[7];
    const float* a2d = (const float*)d_in[8];
    const float* b2  = (const float*)d_in[9];
    float* out = (float*)d_out;

    const int n  = in_sizes[0] / 128;          // 50000
    const int E  = in_sizes[1] / 2;            // 800000
    const int Et = E + n;
    const int nb = (n + 1023) / 1024;

    float *xp1, *h, *xp2;
    cudaGetSymbolAddress((void**)&xp1, g_xp1);
    cudaGetSymbolAddress((void**)&h,   g_h);
    cudaGetSymbolAddress((void**)&xp2, g_xp2);

    const int B = 256;
    const int nwB = (n * 32 + B - 1) / B;      // warp-per-node grids

    // ---- CSR build ----
    init_k     <<<(n + B - 1) / B, B>>>(n);
    detect_k   <<<(4096 + B - 1) / B, B>>>((const unsigned*)ei);
    hist_k     <<<(Et + B - 1) / B, B>>>(ei, E, n);
    scan_bsum_k<<<nb, 256>>>(n);
    scan_top_k <<<1, 64>>>(nb);
    scan_out_k <<<nb, 256>>>(n);
    scatter_k  <<<(Et + B - 1) / B, B>>>(ei, E, n);

    // ---- layer 1 ----
    gemm_k<128, 64><<<(n + 63) / 64, 256>>>(x, W1, xp1, n);
    attn_k<64><<<nwB, B>>>(xp1, a1s, a1d, n);
    agg1_k<<<nwB, B>>>(xp1, b1, h, n);

    // ---- layer 2 ----
    gemm_k<64, 128><<<(n + 127) / 128, 256>>>(h, W2, xp2, n);
    attn_k<32><<<nwB, B>>>(xp2, a2s, a2d, n);
    agg2_k<<<nwB, B>>>(xp2, b2, out, n);
}

// round 4
// speedup vs baseline: 2.8284x; 1.0970x over previous
#include <cuda_runtime.h>
#include <math.h>

// ---------------------------------------------------------------------------
// 2-layer GAT forward, CSR-based.
//   CSR: hist -> multi-block scan -> scatter
//   L1: xp1 = x@W1 (f32x2 GEMM, fused attn dots); fused softmax+agg (+b1, ELU)
//   L2: xp2 = h@W2 (same); fused softmax+agg (+b2, log_softmax)
// ---------------------------------------------------------------------------

#define NN 50000
#define EE 800000
#define ET (EE + NN)
#define NB ((NN + 1023) / 1024)

typedef unsigned long long ull;

// -------- scratch (device globals; no allocation allowed) -------------------
__device__ float  g_xp1[NN * 128];
__device__ float  g_h  [NN * 128];
__device__ float  g_xp2[NN * 64];
__device__ float2 g_as [NN];
__device__ float2 g_ad [NN];
__device__ int    g_deg[NN];
__device__ int    g_row[NN];
__device__ int    g_cur[NN];
__device__ int    g_src[ET];
__device__ int    g_bsum[NB];
__device__ int    g_boff[NB];
__device__ int    g_is32 = 0;   // static init; only ever set to 1 (idempotent across replays)

// -------- packed f32x2 helpers ----------------------------------------------
__device__ __forceinline__ ull pack2(float lo, float hi) {
    ull r; asm("mov.b64 %0, {%1, %2};" : "=l"(r) : "f"(lo), "f"(hi)); return r;
}
__device__ __forceinline__ void unpack2(ull v, float& lo, float& hi) {
    asm("mov.b64 {%0, %1}, %2;" : "=f"(lo), "=f"(hi) : "l"(v));
}
__device__ __forceinline__ ull fma2(ull a, ull b, ull c) {
    ull d; asm("fma.rn.f32x2 %0, %1, %2, %3;" : "=l"(d) : "l"(a), "l"(b), "l"(c));
    return d;
}

// -------- edge decode --------------------------------------------------------
__device__ __forceinline__ void load_edge(const void* ei, int E, int e,
                                          int& s, int& d) {
    if (e >= E) { s = d = e - E; return; }            // self loop
    if (g_is32) {
        const int* p = (const int*)ei;
        s = p[e]; d = p[E + e];
    } else {
        const long long* p = (const long long*)ei;
        s = (int)p[e]; d = (int)p[E + e];
    }
}

// -------- CSR build ----------------------------------------------------------
// int32 layout => odd 32-bit words are node ids (some nonzero);
// int64 layout => odd words are high halves of values < 2^31 => all zero.
__global__ void init_k(const unsigned* w, int n) {
    int i = blockIdx.x * blockDim.x + threadIdx.x;
    if (i < n) g_deg[i] = 0;
    if (i < 4096 && w[2 * i + 1] != 0u) g_is32 = 1;
}
__global__ void hist_k(const void* ei, int E, int n) {
    int e = blockIdx.x * blockDim.x + threadIdx.x;
    if (e >= E + n) return;
    int s, d; load_edge(ei, E, e, s, d);
    atomicAdd(&g_deg[d], 1);
}
__global__ void scan_bsum_k(int n) {
    __shared__ int wsum[8];
    int b = blockIdx.x, t = threadIdx.x;
    int base = b * 1024 + t * 4;
    int s = 0;
#pragma unroll
    for (int j = 0; j < 4; j++) {
        int i = base + j;
        if (i < n) s += g_deg[i];
    }
    int lane = t & 31, w = t >> 5;
#pragma unroll
    for (int o = 16; o; o >>= 1) s += __shfl_xor_sync(0xffffffffu, s, o);
    if (lane == 0) wsum[w] = s;
    __syncthreads();
    if (t == 0) {
        int tot = 0;
#pragma unroll
        for (int j = 0; j < 8; j++) tot += wsum[j];
        g_bsum[b] = tot;
    }
}
__global__ void scan_top_k(int nb) {
    __shared__ int w0tot;
    int t = threadIdx.x, lane = t & 31, w = t >> 5;
    int v = (t < nb) ? g_bsum[t] : 0;
    int inc = v;
#pragma unroll
    for (int o = 1; o < 32; o <<= 1) {
        int x = __shfl_up_sync(0xffffffffu, inc, o);
        if (lane >= o) inc += x;
    }
    if (w == 0 && lane == 31) w0tot = inc;
    __syncthreads();
    if (w == 1) inc += w0tot;
    if (t < nb) g_boff[t] = inc - v;
}
__global__ void scan_out_k(int n) {
    __shared__ int wsum[8], woff[8];
    int b = blockIdx.x, t = threadIdx.x;
    int lane = t & 31, w = t >> 5;
    int base = b * 1024 + t * 4;
    int v[4];
#pragma unroll
    for (int j = 0; j < 4; j++) {
        int i = base + j;
        v[j] = (i < n) ? g_deg[i] : 0;
    }
    int s = v[0] + v[1] + v[2] + v[3];
    int inc = s;
#pragma unroll
    for (int o = 1; o < 32; o <<= 1) {
        int x = __shfl_up_sync(0xffffffffu, inc, o);
        if (lane >= o) inc += x;
    }
    if (lane == 31) wsum[w] = inc;
    __syncthreads();
    if (w == 0) {
        int x = (lane < 8) ? wsum[lane] : 0;
        int i8 = x;
#pragma unroll
        for (int o = 1; o < 8; o <<= 1) {
            int y = __shfl_up_sync(0xffffffffu, i8, o);
            if (lane >= o) i8 += y;
        }
        if (lane < 8) woff[lane] = i8 - x;
    }
    __syncthreads();
    int off = g_boff[b] + woff[w] + (inc - s);
#pragma unroll
    for (int j = 0; j < 4; j++) {
        int i = base + j;
        if (i < n) { g_row[i] = off; g_cur[i] = off; }
        off += v[j];
    }
}
__global__ void scatter_k(const void* ei, int E, int n) {
    int e = blockIdx.x * blockDim.x + threadIdx.x;
    if (e >= E + n) return;
    int s, d; load_edge(ei, E, e, s, d);
    int pos = atomicAdd(&g_cur[d], 1);
    g_src[pos] = s;
}

// -------- f32x2 GEMM + fused attn dots --------------------------------------
// Y[n,C] = X[n,128] @ W[128,C];   g_as/g_ad[r] = per-head dots with As/Ad[C]
template <int C, int BM>
__global__ void gemm_attn_k(const float* __restrict__ X, const float* __restrict__ W,
                            float* __restrict__ Y, const float* __restrict__ As,
                            const float* __restrict__ Ad, int n) {
    constexpr int K = 128, BK = 16, TM = 8, TN = 4;
    constexpr int TCOLS = C / TN;               // 32 (C=128) / 16 (C=64)
    constexpr int NT    = (BM / TM) * TCOLS;    // 256
    constexpr int GW    = (C / 2) / TN;         // lanes per head group: 16 / 8
    __shared__ __align__(16) float Xs[BK][BM];
    __shared__ __align__(16) float Ws[BK][C];
    const int tid = threadIdx.x;
    const int tc = tid % TCOLS, tr = tid / TCOLS;
    const int row0 = blockIdx.x * BM;
    ull acc2[TM / 2][TN];
#pragma unroll
    for (int ip = 0; ip < TM / 2; ip++)
#pragma unroll
        for (int j = 0; j < TN; j++) acc2[ip][j] = pack2(0.f, 0.f);

    for (int kt = 0; kt < K; kt += BK) {
#pragma unroll
        for (int idx = tid; idx < BM * BK / 4; idx += NT) {
            int m = idx / (BK / 4), q = idx % (BK / 4);
            float4 v = make_float4(0.f, 0.f, 0.f, 0.f);
            if (row0 + m < n)
                v = *(const float4*)&X[(long long)(row0 + m) * K + kt + q * 4];
            Xs[q * 4 + 0][m] = v.x; Xs[q * 4 + 1][m] = v.y;
            Xs[q * 4 + 2][m] = v.z; Xs[q * 4 + 3][m] = v.w;
        }
#pragma unroll
        for (int idx = tid; idx < BK * C / 4; idx += NT) {
            int k = idx / (C / 4), q = idx % (C / 4);
            *(float4*)&Ws[k][q * 4] = *(const float4*)&W[(kt + k) * C + q * 4];
        }
        __syncthreads();
#pragma unroll
        for (int k = 0; k < BK; k++) {
            // X pairs: natural f32x2 via 64-bit shared loads (broadcast in-warp)
            ull x2[TM / 2];
#pragma unroll
            for (int ip = 0; ip < TM / 2; ip++)
                x2[ip] = *(const ull*)&Xs[k][tr * TM + 2 * ip];
            float4 w = *(const float4*)&Ws[k][tc * TN];
            ull wd[TN] = {pack2(w.x, w.x), pack2(w.y, w.y),
                          pack2(w.z, w.z), pack2(w.w, w.w)};
#pragma unroll
            for (int ip = 0; ip < TM / 2; ip++)
#pragma unroll
                for (int j = 0; j < TN; j++)
                    acc2[ip][j] = fma2(x2[ip], wd[j], acc2[ip][j]);
        }
        __syncthreads();
    }
    // unpack
    float accf[TM][TN];
#pragma unroll
    for (int ip = 0; ip < TM / 2; ip++)
#pragma unroll
        for (int j = 0; j < TN; j++)
            unpack2(acc2[ip][j], accf[2 * ip][j], accf[2 * ip + 1][j]);
    // store
#pragma unroll
    for (int i = 0; i < TM; i++) {
        int r = row0 + tr * TM + i;
        if (r < n)
            *(float4*)&Y[(long long)r * C + tc * TN] =
                make_float4(accf[i][0], accf[i][1], accf[i][2], accf[i][3]);
    }
    // fused attn dots: per-row per-head sums of accf * As / Ad
    float4 av = ((const float4*)As)[tc];
    float4 dv = ((const float4*)Ad)[tc];
    float sdot[TM], ddot[TM];
#pragma unroll
    for (int i = 0; i < TM; i++) {
        sdot[i] = accf[i][0] * av.x + accf[i][1] * av.y +
                  accf[i][2] * av.z + accf[i][3] * av.w;
        ddot[i] = accf[i][0] * dv.x + accf[i][1] * dv.y +
                  accf[i][2] * dv.z + accf[i][3] * dv.w;
#pragma unroll
        for (int o = GW / 2; o; o >>= 1) {
            sdot[i] += __shfl_xor_sync(0xffffffffu, sdot[i], o);
            ddot[i] += __shfl_xor_sync(0xffffffffu, ddot[i], o);
        }
    }
    if ((tc & (GW - 1)) == 0) {
        int h = (tc / GW) & 1;
#pragma unroll
        for (int i = 0; i < TM; i++) {
            int r = row0 + tr * TM + i;
            if (r < n) {
                ((float*)g_as)[r * 2 + h] = sdot[i];
                ((float*)g_ad)[r * 2 + h] = ddot[i];
            }
        }
    }
}

// -------- fused softmax+agg, layer 1: h = ELU((sum p*xp)/den + b1) ----------
__global__ void agg1_k(const float* __restrict__ xp, const float* __restrict__ b1,
                       float* __restrict__ h, int n) {
    int g = blockIdx.x * blockDim.x + threadIdx.x;
    int node = g >> 5, lane = g & 31;
    if (node >= n) return;
    int start = g_row[node], deg = g_deg[node];
    float2 ad = g_ad[node];
    float4 acc = make_float4(0.f, 0.f, 0.f, 0.f);
    float d0 = 0.f, d1 = 0.f;
    const float4* xp4 = (const float4*)xp;

    if (deg <= 32) {                       // fast path: single gather of g_as
        int s = 0; float e0 = -1e30f, e1 = -1e30f;
        if (lane < deg) {
            s = g_src[start + lane];
            float2 as = g_as[s];
            e0 = as.x + ad.x; e0 = e0 > 0.f ? e0 : 0.2f * e0;
            e1 = as.y + ad.y; e1 = e1 > 0.f ? e1 : 0.2f * e1;
        }
        float m0 = e0, m1 = e1;
#pragma unroll
        for (int o = 16; o; o >>= 1) {
            m0 = fmaxf(m0, __shfl_xor_sync(0xffffffffu, m0, o));
            m1 = fmaxf(m1, __shfl_xor_sync(0xffffffffu, m1, o));
        }
        float p0 = 0.f, p1 = 0.f;
        if (lane < deg) { p0 = expf(e0 - m0); p1 = expf(e1 - m1); }
        d0 = p0; d1 = p1;
        for (int j = 0; j < deg; j++) {
            int   ss = __shfl_sync(0xffffffffu, s,  j);
            float f0 = __shfl_sync(0xffffffffu, p0, j);
            float f1 = __shfl_sync(0xffffffffu, p1, j);
            float a  = lane < 16 ? f0 : f1;
            float4 v = xp4[(long long)ss * 32 + lane];
            acc.x = fmaf(v.x, a, acc.x); acc.y = fmaf(v.y, a, acc.y);
            acc.z = fmaf(v.z, a, acc.z); acc.w = fmaf(v.w, a, acc.w);
        }
    } else {
        float m0 = -1e30f, m1 = -1e30f;
        for (int i = lane; i < deg; i += 32) {
            float2 as = g_as[g_src[start + i]];
            float e0 = as.x + ad.x; e0 = e0 > 0.f ? e0 : 0.2f * e0;
            float e1 = as.y + ad.y; e1 = e1 > 0.f ? e1 : 0.2f * e1;
            m0 = fmaxf(m0, e0); m1 = fmaxf(m1, e1);
        }
#pragma unroll
        for (int o = 16; o; o >>= 1) {
            m0 = fmaxf(m0, __shfl_xor_sync(0xffffffffu, m0, o));
            m1 = fmaxf(m1, __shfl_xor_sync(0xffffffffu, m1, o));
        }
        int base = 0;
        for (; base + 32 <= deg; base += 32) {
            int s = g_src[start + base + lane];
            float2 as = g_as[s];
            float e0 = as.x + ad.x; e0 = e0 > 0.f ? e0 : 0.2f * e0;
            float e1 = as.y + ad.y; e1 = e1 > 0.f ? e1 : 0.2f * e1;
            float p0 = expf(e0 - m0), p1 = expf(e1 - m1);
            d0 += p0; d1 += p1;
#pragma unroll 4
            for (int j = 0; j < 32; j++) {
                int   ss = __shfl_sync(0xffffffffu, s,  j);
                float f0 = __shfl_sync(0xffffffffu, p0, j);
                float f1 = __shfl_sync(0xffffffffu, p1, j);
                float a  = lane < 16 ? f0 : f1;
                float4 v = xp4[(long long)ss * 32 + lane];
                acc.x = fmaf(v.x, a, acc.x); acc.y = fmaf(v.y, a, acc.y);
                acc.z = fmaf(v.z, a, acc.z); acc.w = fmaf(v.w, a, acc.w);
            }
        }
        int rem = deg - base;
        if (rem) {
            int s = 0; float p0 = 0.f, p1 = 0.f;
            if (lane < rem) {
                s = g_src[start + base + lane];
                float2 as = g_as[s];
                float e0 = as.x + ad.x; e0 = e0 > 0.f ? e0 : 0.2f * e0;
                float e1 = as.y + ad.y; e1 = e1 > 0.f ? e1 : 0.2f * e1;
                p0 = expf(e0 - m0); p1 = expf(e1 - m1);
            }
            d0 += p0; d1 += p1;
            for (int j = 0; j < rem; j++) {
                int   ss = __shfl_sync(0xffffffffu, s,  j);
                float f0 = __shfl_sync(0xffffffffu, p0, j);
                float f1 = __shfl_sync(0xffffffffu, p1, j);
                float a  = lane < 16 ? f0 : f1;
                float4 v = xp4[(long long)ss * 32 + lane];
                acc.x = fmaf(v.x, a, acc.x); acc.y = fmaf(v.y, a, acc.y);
                acc.z = fmaf(v.z, a, acc.z); acc.w = fmaf(v.w, a, acc.w);
            }
        }
    }
#pragma unroll
    for (int o = 16; o; o >>= 1) {
        d0 += __shfl_xor_sync(0xffffffffu, d0, o);
        d1 += __shfl_xor_sync(0xffffffffu, d1, o);
    }
    float r = 1.f / (lane < 16 ? d0 : d1);
    float4 bb = ((const float4*)b1)[lane];
    acc.x = fmaf(acc.x, r, bb.x); acc.y = fmaf(acc.y, r, bb.y);
    acc.z = fmaf(acc.z, r, bb.z); acc.w = fmaf(acc.w, r, bb.w);
    acc.x = acc.x > 0.f ? acc.x : expm1f(acc.x);
    acc.y = acc.y > 0.f ? acc.y : expm1f(acc.y);
    acc.z = acc.z > 0.f ? acc.z : expm1f(acc.z);
    acc.w = acc.w > 0.f ? acc.w : expm1f(acc.w);
    ((float4*)h)[(long long)node * 32 + lane] = acc;
}

// -------- fused softmax+agg, layer 2 (+bias, log_softmax) -------------------
__global__ void agg2_k(const float* __restrict__ xp, const float* __restrict__ b2,
                       float* __restrict__ out, int n) {
    int g = blockIdx.x * blockDim.x + threadIdx.x;
    int node = g >> 5, lane = g & 31;
    if (node >= n) return;
    int start = g_row[node], deg = g_deg[node];
    float2 ad = g_ad[node];
    float ax = 0.f, ay = 0.f, d0 = 0.f, d1 = 0.f;
    const float2* xp2 = (const float2*)xp;

    if (deg <= 32) {
        int s = 0; float e0 = -1e30f, e1 = -1e30f;
        if (lane < deg) {
            s = g_src[start + lane];
            float2 as = g_as[s];
            e0 = as.x + ad.x; e0 = e0 > 0.f ? e0 : 0.2f * e0;
            e1 = as.y + ad.y; e1 = e1 > 0.f ? e1 : 0.2f * e1;
        }
        float m0 = e0, m1 = e1;
#pragma unroll
        for (int o = 16; o; o >>= 1) {
            m0 = fmaxf(m0, __shfl_xor_sync(0xffffffffu, m0, o));
            m1 = fmaxf(m1, __shfl_xor_sync(0xffffffffu, m1, o));
        }
        float p0 = 0.f, p1 = 0.f;
        if (lane < deg) { p0 = expf(e0 - m0); p1 = expf(e1 - m1); }
        d0 = p0; d1 = p1;
        for (int j = 0; j < deg; j++) {
            int   ss = __shfl_sync(0xffffffffu, s,  j);
            float f0 = __shfl_sync(0xffffffffu, p0, j);
            float f1 = __shfl_sync(0xffffffffu, p1, j);
            float a  = lane < 16 ? f0 : f1;
            float2 v = xp2[(long long)ss * 32 + lane];
            ax = fmaf(v.x, a, ax); ay = fmaf(v.y, a, ay);
        }
    } else {
        float m0 = -1e30f, m1 = -1e30f;
        for (int i = lane; i < deg; i += 32) {
            float2 as = g_as[g_src[start + i]];
            float e0 = as.x + ad.x; e0 = e0 > 0.f ? e0 : 0.2f * e0;
            float e1 = as.y + ad.y; e1 = e1 > 0.f ? e1 : 0.2f * e1;
            m0 = fmaxf(m0, e0); m1 = fmaxf(m1, e1);
        }
#pragma unroll
        for (int o = 16; o; o >>= 1) {
            m0 = fmaxf(m0, __shfl_xor_sync(0xffffffffu, m0, o));
            m1 = fmaxf(m1, __shfl_xor_sync(0xffffffffu, m1, o));
        }
        int base = 0;
        for (; base + 32 <= deg; base += 32) {
            int s = g_src[start + base + lane];
            float2 as = g_as[s];
            float e0 = as.x + ad.x; e0 = e0 > 0.f ? e0 : 0.2f * e0;
            float e1 = as.y + ad.y; e1 = e1 > 0.f ? e1 : 0.2f * e1;
            float p0 = expf(e0 - m0), p1 = expf(e1 - m1);
            d0 += p0; d1 += p1;
#pragma unroll 4
            for (int j = 0; j < 32; j++) {
                int   ss = __shfl_sync(0xffffffffu, s,  j);
                float f0 = __shfl_sync(0xffffffffu, p0, j);
                float f1 = __shfl_sync(0xffffffffu, p1, j);
                float a  = lane < 16 ? f0 : f1;
                float2 v = xp2[(long long)ss * 32 + lane];
                ax = fmaf(v.x, a, ax); ay = fmaf(v.y, a, ay);
            }
        }
        int rem = deg - base;
        if (rem) {
            int s = 0; float p0 = 0.f, p1 = 0.f;
            if (lane < rem) {
                s = g_src[start + base + lane];
                float2 as = g_as[s];
                float e0 = as.x + ad.x; e0 = e0 > 0.f ? e0 : 0.2f * e0;
                float e1 = as.y + ad.y; e1 = e1 > 0.f ? e1 : 0.2f * e1;
                p0 = expf(e0 - m0); p1 = expf(e1 - m1);
            }
            d0 += p0; d1 += p1;
            for (int j = 0; j < rem; j++) {
                int   ss = __shfl_sync(0xffffffffu, s,  j);
                float f0 = __shfl_sync(0xffffffffu, p0, j);
                float f1 = __shfl_sync(0xffffffffu, p1, j);
                float a  = lane < 16 ? f0 : f1;
                float2 v = xp2[(long long)ss * 32 + lane];
                ax = fmaf(v.x, a, ax); ay = fmaf(v.y, a, ay);
            }
        }
    }
#pragma unroll
    for (int o = 16; o; o >>= 1) {
        d0 += __shfl_xor_sync(0xffffffffu, d0, o);
        d1 += __shfl_xor_sync(0xffffffffu, d1, o);
    }
    float r = 1.f / (lane < 16 ? d0 : d1);
    float2 bb = ((const float2*)b2)[lane];
    float v0 = fmaf(ax, r, bb.x), v1 = fmaf(ay, r, bb.y);
    float m = fmaxf(v0, v1);
#pragma unroll
    for (int o = 16; o; o >>= 1) m = fmaxf(m, __shfl_xor_sync(0xffffffffu, m, o));
    float sm = expf(v0 - m) + expf(v1 - m);
#pragma unroll
    for (int o = 16; o; o >>= 1) sm += __shfl_xor_sync(0xffffffffu, sm, o);
    float lse = m + logf(sm);
    ((float2*)out)[(long long)node * 32 + lane] = make_float2(v0 - lse, v1 - lse);
}

// ---------------------------------------------------------------------------
extern "C" void kernel_launch(void* const* d_in, const int* in_sizes, int n_in,
                              void* d_out, int out_size) {
    const float* x   = (const float*)d_in[0];
    const void*  ei  = d_in[1];
    const float* W1  = (const float*)d_in[2];
    const float* a1s = (const float*)d_in[3];
    const float* a1d = (const float*)d_in[4];
    const float* b1  = (const float*)d_in[5];
    const float* W2  = (const float*)d_in[6];
    const float* a2s = (const float*)d_in[7];
    const float* a2d = (const float*)d_in[8];
    const float* b2  = (const float*)d_in[9];
    float* out = (float*)d_out;

    const int n  = in_sizes[0] / 128;          // 50000
    const int E  = in_sizes[1] / 2;            // 800000
    const int Et = E + n;
    const int nb = (n + 1023) / 1024;

    float *xp1, *h, *xp2;
    cudaGetSymbolAddress((void**)&xp1, g_xp1);
    cudaGetSymbolAddress((void**)&h,   g_h);
    cudaGetSymbolAddress((void**)&xp2, g_xp2);

    const int B = 256;
    const int nwB = (n * 32 + B - 1) / B;

    // ---- CSR build ----
    init_k     <<<(n + B - 1) / B, B>>>((const unsigned*)ei, n);
    hist_k     <<<(Et + B - 1) / B, B>>>(ei, E, n);
    scan_bsum_k<<<nb, 256>>>(n);
    scan_top_k <<<1, 64>>>(nb);
    scan_out_k <<<nb, 256>>>(n);
    scatter_k  <<<(Et + B - 1) / B, B>>>(ei, E, n);

    // ---- layer 1 ----
    gemm_attn_k<128, 64><<<(n + 63) / 64, 256>>>(x, W1, xp1, a1s, a1d, n);
    agg1_k<<<nwB, B>>>(xp1, b1, h, n);

    // ---- layer 2 ----
    gemm_attn_k<64, 128><<<(n + 127) / 128, 256>>>(h, W2, xp2, a2s, a2d, n);
    agg2_k<<<nwB, B>>>(xp2, b2, out, n);
}

// round 5
// speedup vs baseline: 3.0548x; 1.0800x over previous
#include <cuda_runtime.h>
#include <math.h>

// ---------------------------------------------------------------------------
// 2-layer GAT forward, CSR-based, with forked graph capture:
//   side stream: CSR build (init/hist/scan x3/scatter)   } run
//   main stream: gemm1 (+fused attn dots)                } concurrently
//   join -> agg1 -> gemm2(+attn) -> agg2
// ---------------------------------------------------------------------------

#define NN 50000
#define EE 800000
#define ET (EE + NN)
#define NB ((NN + 1023) / 1024)

typedef unsigned long long ull;

// -------- scratch (device globals; no allocation allowed) -------------------
__device__ float  g_xp1[NN * 128];
__device__ float  g_h  [NN * 128];
__device__ float  g_xp2[NN * 64];
__device__ float2 g_as [NN];
__device__ float2 g_ad [NN];
__device__ int    g_deg[NN];
__device__ int    g_row[NN];
__device__ int    g_cur[NN];
__device__ int    g_src[ET];
__device__ int    g_bsum[NB];
__device__ int    g_boff[NB];
__device__ int    g_is32 = 0;   // only ever set to 1 (idempotent across replays)

// -------- packed f32x2 helpers ----------------------------------------------
__device__ __forceinline__ ull pack2(float lo, float hi) {
    ull r; asm("mov.b64 %0, {%1, %2};" : "=l"(r) : "f"(lo), "f"(hi)); return r;
}
__device__ __forceinline__ void unpack2(ull v, float& lo, float& hi) {
    asm("mov.b64 {%0, %1}, %2;" : "=f"(lo), "=f"(hi) : "l"(v));
}
__device__ __forceinline__ ull fma2(ull a, ull b, ull c) {
    ull d; asm("fma.rn.f32x2 %0, %1, %2, %3;" : "=l"(d) : "l"(a), "l"(b), "l"(c));
    return d;
}

// -------- edge decode --------------------------------------------------------
__device__ __forceinline__ void load_edge(const void* ei, int E, int e,
                                          int& s, int& d) {
    if (e >= E) { s = d = e - E; return; }            // self loop
    if (g_is32) {
        const int* p = (const int*)ei;
        s = p[e]; d = p[E + e];
    } else {
        const long long* p = (const long long*)ei;
        s = (int)p[e]; d = (int)p[E + e];
    }
}

// -------- CSR build ----------------------------------------------------------
// int32 layout => odd 32-bit words are node ids (some nonzero);
// int64 layout => odd words are high halves of values < 2^31 => all zero.
__global__ void init_k(const unsigned* w, int n) {
    int i = blockIdx.x * blockDim.x + threadIdx.x;
    if (i < n) g_deg[i] = 0;
    if (i < 4096 && w[2 * i + 1] != 0u) g_is32 = 1;
}
__global__ void hist_k(const void* ei, int E, int n) {
    int e = blockIdx.x * blockDim.x + threadIdx.x;
    if (e >= E + n) return;
    int s, d; load_edge(ei, E, e, s, d);
    atomicAdd(&g_deg[d], 1);
}
__global__ void scan_bsum_k(int n) {
    __shared__ int wsum[8];
    int b = blockIdx.x, t = threadIdx.x;
    int base = b * 1024 + t * 4;
    int s = 0;
#pragma unroll
    for (int j = 0; j < 4; j++) {
        int i = base + j;
        if (i < n) s += g_deg[i];
    }
    int lane = t & 31, w = t >> 5;
#pragma unroll
    for (int o = 16; o; o >>= 1) s += __shfl_xor_sync(0xffffffffu, s, o);
    if (lane == 0) wsum[w] = s;
    __syncthreads();
    if (t == 0) {
        int tot = 0;
#pragma unroll
        for (int j = 0; j < 8; j++) tot += wsum[j];
        g_bsum[b] = tot;
    }
}
__global__ void scan_top_k(int nb) {
    __shared__ int w0tot;
    int t = threadIdx.x, lane = t & 31, w = t >> 5;
    int v = (t < nb) ? g_bsum[t] : 0;
    int inc = v;
#pragma unroll
    for (int o = 1; o < 32; o <<= 1) {
        int x = __shfl_up_sync(0xffffffffu, inc, o);
        if (lane >= o) inc += x;
    }
    if (w == 0 && lane == 31) w0tot = inc;
    __syncthreads();
    if (w == 1) inc += w0tot;
    if (t < nb) g_boff[t] = inc - v;
}
__global__ void scan_out_k(int n) {
    __shared__ int wsum[8], woff[8];
    int b = blockIdx.x, t = threadIdx.x;
    int lane = t & 31, w = t >> 5;
    int base = b * 1024 + t * 4;
    int v[4];
#pragma unroll
    for (int j = 0; j < 4; j++) {
        int i = base + j;
        v[j] = (i < n) ? g_deg[i] : 0;
    }
    int s = v[0] + v[1] + v[2] + v[3];
    int inc = s;
#pragma unroll
    for (int o = 1; o < 32; o <<= 1) {
        int x = __shfl_up_sync(0xffffffffu, inc, o);
        if (lane >= o) inc += x;
    }
    if (lane == 31) wsum[w] = inc;
    __syncthreads();
    if (w == 0) {
        int x = (lane < 8) ? wsum[lane] : 0;
        int i8 = x;
#pragma unroll
        for (int o = 1; o < 8; o <<= 1) {
            int y = __shfl_up_sync(0xffffffffu, i8, o);
            if (lane >= o) i8 += y;
        }
        if (lane < 8) woff[lane] = i8 - x;
    }
    __syncthreads();
    int off = g_boff[b] + woff[w] + (inc - s);
#pragma unroll
    for (int j = 0; j < 4; j++) {
        int i = base + j;
        if (i < n) { g_row[i] = off; g_cur[i] = off; }
        off += v[j];
    }
}
__global__ void scatter_k(const void* ei, int E, int n) {
    int e = blockIdx.x * blockDim.x + threadIdx.x;
    if (e >= E + n) return;
    int s, d; load_edge(ei, E, e, s, d);
    int pos = atomicAdd(&g_cur[d], 1);
    g_src[pos] = s;
}

// -------- f32x2 GEMM + fused attn dots --------------------------------------
template <int C, int BM>
__global__ void gemm_attn_k(const float* __restrict__ X, const float* __restrict__ W,
                            float* __restrict__ Y, const float* __restrict__ As,
                            const float* __restrict__ Ad, int n) {
    constexpr int K = 128, BK = 16, TM = 8, TN = 4;
    constexpr int TCOLS = C / TN;
    constexpr int NT    = (BM / TM) * TCOLS;    // 256
    constexpr int GW    = (C / 2) / TN;         // lanes per head group
    __shared__ __align__(16) float Xs[BK][BM];
    __shared__ __align__(16) float Ws[BK][C];
    const int tid = threadIdx.x;
    const int tc = tid % TCOLS, tr = tid / TCOLS;
    const int row0 = blockIdx.x * BM;
    ull acc2[TM / 2][TN];
#pragma unroll
    for (int ip = 0; ip < TM / 2; ip++)
#pragma unroll
        for (int j = 0; j < TN; j++) acc2[ip][j] = pack2(0.f, 0.f);

    for (int kt = 0; kt < K; kt += BK) {
#pragma unroll
        for (int idx = tid; idx < BM * BK / 4; idx += NT) {
            int m = idx / (BK / 4), q = idx % (BK / 4);
            float4 v = make_float4(0.f, 0.f, 0.f, 0.f);
            if (row0 + m < n)
                v = *(const float4*)&X[(long long)(row0 + m) * K + kt + q * 4];
            Xs[q * 4 + 0][m] = v.x; Xs[q * 4 + 1][m] = v.y;
            Xs[q * 4 + 2][m] = v.z; Xs[q * 4 + 3][m] = v.w;
        }
#pragma unroll
        for (int idx = tid; idx < BK * C / 4; idx += NT) {
            int k = idx / (C / 4), q = idx % (C / 4);
            *(float4*)&Ws[k][q * 4] = *(const float4*)&W[(kt + k) * C + q * 4];
        }
        __syncthreads();
#pragma unroll
        for (int k = 0; k < BK; k++) {
            ull x2[TM / 2];
#pragma unroll
            for (int ip = 0; ip < TM / 2; ip++)
                x2[ip] = *(const ull*)&Xs[k][tr * TM + 2 * ip];
            float4 w = *(const float4*)&Ws[k][tc * TN];
            ull wd[TN] = {pack2(w.x, w.x), pack2(w.y, w.y),
                          pack2(w.z, w.z), pack2(w.w, w.w)};
#pragma unroll
            for (int ip = 0; ip < TM / 2; ip++)
#pragma unroll
                for (int j = 0; j < TN; j++)
                    acc2[ip][j] = fma2(x2[ip], wd[j], acc2[ip][j]);
        }
        __syncthreads();
    }
    float accf[TM][TN];
#pragma unroll
    for (int ip = 0; ip < TM / 2; ip++)
#pragma unroll
        for (int j = 0; j < TN; j++)
            unpack2(acc2[ip][j], accf[2 * ip][j], accf[2 * ip + 1][j]);
#pragma unroll
    for (int i = 0; i < TM; i++) {
        int r = row0 + tr * TM + i;
        if (r < n)
            *(float4*)&Y[(long long)r * C + tc * TN] =
                make_float4(accf[i][0], accf[i][1], accf[i][2], accf[i][3]);
    }
    float4 av = ((const float4*)As)[tc];
    float4 dv = ((const float4*)Ad)[tc];
    float sdot[TM], ddot[TM];
#pragma unroll
    for (int i = 0; i < TM; i++) {
        sdot[i] = accf[i][0] * av.x + accf[i][1] * av.y +
                  accf[i][2] * av.z + accf[i][3] * av.w;
        ddot[i] = accf[i][0] * dv.x + accf[i][1] * dv.y +
                  accf[i][2] * dv.z + accf[i][3] * dv.w;
#pragma unroll
        for (int o = GW / 2; o; o >>= 1) {
            sdot[i] += __shfl_xor_sync(0xffffffffu, sdot[i], o);
            ddot[i] += __shfl_xor_sync(0xffffffffu, ddot[i], o);
        }
    }
    if ((tc & (GW - 1)) == 0) {
        int h = (tc / GW) & 1;
#pragma unroll
        for (int i = 0; i < TM; i++) {
            int r = row0 + tr * TM + i;
            if (r < n) {
                ((float*)g_as)[r * 2 + h] = sdot[i];
                ((float*)g_ad)[r * 2 + h] = ddot[i];
            }
        }
    }
}

// -------- fused softmax+agg, layer 1 ----------------------------------------
__global__ void agg1_k(const float* __restrict__ xp, const float* __restrict__ b1,
                       float* __restrict__ h, int n) {
    int g = blockIdx.x * blockDim.x + threadIdx.x;
    int node = g >> 5, lane = g & 31;
    if (node >= n) return;
    int start = g_row[node], deg = g_deg[node];
    float2 ad = g_ad[node];
    float4 acc = make_float4(0.f, 0.f, 0.f, 0.f);
    float d0 = 0.f, d1 = 0.f;
    const float4* xp4 = (const float4*)xp;

    if (deg <= 32) {
        int s = 0; float e0 = -1e30f, e1 = -1e30f;
        if (lane < deg) {
            s = g_src[start + lane];
            float2 as = g_as[s];
            e0 = as.x + ad.x; e0 = e0 > 0.f ? e0 : 0.2f * e0;
            e1 = as.y + ad.y; e1 = e1 > 0.f ? e1 : 0.2f * e1;
        }
        float m0 = e0, m1 = e1;
#pragma unroll
        for (int o = 16; o; o >>= 1) {
            m0 = fmaxf(m0, __shfl_xor_sync(0xffffffffu, m0, o));
            m1 = fmaxf(m1, __shfl_xor_sync(0xffffffffu, m1, o));
        }
        float p0 = 0.f, p1 = 0.f;
        if (lane < deg) { p0 = expf(e0 - m0); p1 = expf(e1 - m1); }
        d0 = p0; d1 = p1;
        for (int j = 0; j < deg; j++) {
            int   ss = __shfl_sync(0xffffffffu, s,  j);
            float f0 = __shfl_sync(0xffffffffu, p0, j);
            float f1 = __shfl_sync(0xffffffffu, p1, j);
            float a  = lane < 16 ? f0 : f1;
            float4 v = xp4[(long long)ss * 32 + lane];
            acc.x = fmaf(v.x, a, acc.x); acc.y = fmaf(v.y, a, acc.y);
            acc.z = fmaf(v.z, a, acc.z); acc.w = fmaf(v.w, a, acc.w);
        }
    } else {
        float m0 = -1e30f, m1 = -1e30f;
        for (int i = lane; i < deg; i += 32) {
            float2 as = g_as[g_src[start + i]];
            float e0 = as.x + ad.x; e0 = e0 > 0.f ? e0 : 0.2f * e0;
            float e1 = as.y + ad.y; e1 = e1 > 0.f ? e1 : 0.2f * e1;
            m0 = fmaxf(m0, e0); m1 = fmaxf(m1, e1);
        }
#pragma unroll
        for (int o = 16; o; o >>= 1) {
            m0 = fmaxf(m0, __shfl_xor_sync(0xffffffffu, m0, o));
            m1 = fmaxf(m1, __shfl_xor_sync(0xffffffffu, m1, o));
        }
        int base = 0;
        for (; base + 32 <= deg; base += 32) {
            int s = g_src[start + base + lane];
            float2 as = g_as[s];
            float e0 = as.x + ad.x; e0 = e0 > 0.f ? e0 : 0.2f * e0;
            float e1 = as.y + ad.y; e1 = e1 > 0.f ? e1 : 0.2f * e1;
            float p0 = expf(e0 - m0), p1 = expf(e1 - m1);
            d0 += p0; d1 += p1;
#pragma unroll 4
            for (int j = 0; j < 32; j++) {
                int   ss = __shfl_sync(0xffffffffu, s,  j);
                float f0 = __shfl_sync(0xffffffffu, p0, j);
                float f1 = __shfl_sync(0xffffffffu, p1, j);
                float a  = lane < 16 ? f0 : f1;
                float4 v = xp4[(long long)ss * 32 + lane];
                acc.x = fmaf(v.x, a, acc.x); acc.y = fmaf(v.y, a, acc.y);
                acc.z = fmaf(v.z, a, acc.z); acc.w = fmaf(v.w, a, acc.w);
            }
        }
        int rem = deg - base;
        if (rem) {
            int s = 0; float p0 = 0.f, p1 = 0.f;
            if (lane < rem) {
                s = g_src[start + base + lane];
                float2 as = g_as[s];
                float e0 = as.x + ad.x; e0 = e0 > 0.f ? e0 : 0.2f * e0;
                float e1 = as.y + ad.y; e1 = e1 > 0.f ? e1 : 0.2f * e1;
                p0 = expf(e0 - m0); p1 = expf(e1 - m1);
            }
            d0 += p0; d1 += p1;
            for (int j = 0; j < rem; j++) {
                int   ss = __shfl_sync(0xffffffffu, s,  j);
                float f0 = __shfl_sync(0xffffffffu, p0, j);
                float f1 = __shfl_sync(0xffffffffu, p1, j);
                float a  = lane < 16 ? f0 : f1;
                float4 v = xp4[(long long)ss * 32 + lane];
                acc.x = fmaf(v.x, a, acc.x); acc.y = fmaf(v.y, a, acc.y);
                acc.z = fmaf(v.z, a, acc.z); acc.w = fmaf(v.w, a, acc.w);
            }
        }
    }
#pragma unroll
    for (int o = 16; o; o >>= 1) {
        d0 += __shfl_xor_sync(0xffffffffu, d0, o);
        d1 += __shfl_xor_sync(0xffffffffu, d1, o);
    }
    float r = 1.f / (lane < 16 ? d0 : d1);
    float4 bb = ((const float4*)b1)[lane];
    acc.x = fmaf(acc.x, r, bb.x); acc.y = fmaf(acc.y, r, bb.y);
    acc.z = fmaf(acc.z, r, bb.z); acc.w = fmaf(acc.w, r, bb.w);
    acc.x = acc.x > 0.f ? acc.x : expm1f(acc.x);
    acc.y = acc.y > 0.f ? acc.y : expm1f(acc.y);
    acc.z = acc.z > 0.f ? acc.z : expm1f(acc.z);
    acc.w = acc.w > 0.f ? acc.w : expm1f(acc.w);
    ((float4*)h)[(long long)node * 32 + lane] = acc;
}

// -------- fused softmax+agg, layer 2 (+bias, log_softmax) -------------------
__global__ void agg2_k(const float* __restrict__ xp, const float* __restrict__ b2,
                       float* __restrict__ out, int n) {
    int g = blockIdx.x * blockDim.x + threadIdx.x;
    int node = g >> 5, lane = g & 31;
    if (node >= n) return;
    int start = g_row[node], deg = g_deg[node];
    float2 ad = g_ad[node];
    float ax = 0.f, ay = 0.f, d0 = 0.f, d1 = 0.f;
    const float2* xp2 = (const float2*)xp;

    if (deg <= 32) {
        int s = 0; float e0 = -1e30f, e1 = -1e30f;
        if (lane < deg) {
            s = g_src[start + lane];
            float2 as = g_as[s];
            e0 = as.x + ad.x; e0 = e0 > 0.f ? e0 : 0.2f * e0;
            e1 = as.y + ad.y; e1 = e1 > 0.f ? e1 : 0.2f * e1;
        }
        float m0 = e0, m1 = e1;
#pragma unroll
        for (int o = 16; o; o >>= 1) {
            m0 = fmaxf(m0, __shfl_xor_sync(0xffffffffu, m0, o));
            m1 = fmaxf(m1, __shfl_xor_sync(0xffffffffu, m1, o));
        }
        float p0 = 0.f, p1 = 0.f;
        if (lane < deg) { p0 = expf(e0 - m0); p1 = expf(e1 - m1); }
        d0 = p0; d1 = p1;
        for (int j = 0; j < deg; j++) {
            int   ss = __shfl_sync(0xffffffffu, s,  j);
            float f0 = __shfl_sync(0xffffffffu, p0, j);
            float f1 = __shfl_sync(0xffffffffu, p1, j);
            float a  = lane < 16 ? f0 : f1;
            float2 v = xp2[(long long)ss * 32 + lane];
            ax = fmaf(v.x, a, ax); ay = fmaf(v.y, a, ay);
        }
    } else {
        float m0 = -1e30f, m1 = -1e30f;
        for (int i = lane; i < deg; i += 32) {
            float2 as = g_as[g_src[start + i]];
            float e0 = as.x + ad.x; e0 = e0 > 0.f ? e0 : 0.2f * e0;
            float e1 = as.y + ad.y; e1 = e1 > 0.f ? e1 : 0.2f * e1;
            m0 = fmaxf(m0, e0); m1 = fmaxf(m1, e1);
        }
#pragma unroll
        for (int o = 16; o; o >>= 1) {
            m0 = fmaxf(m0, __shfl_xor_sync(0xffffffffu, m0, o));
            m1 = fmaxf(m1, __shfl_xor_sync(0xffffffffu, m1, o));
        }
        int base = 0;
        for (; base + 32 <= deg; base += 32) {
            int s = g_src[start + base + lane];
            float2 as = g_as[s];
            float e0 = as.x + ad.x; e0 = e0 > 0.f ? e0 : 0.2f * e0;
            float e1 = as.y + ad.y; e1 = e1 > 0.f ? e1 : 0.2f * e1;
            float p0 = expf(e0 - m0), p1 = expf(e1 - m1);
            d0 += p0; d1 += p1;
#pragma unroll 4
            for (int j = 0; j < 32; j++) {
                int   ss = __shfl_sync(0xffffffffu, s,  j);
                float f0 = __shfl_sync(0xffffffffu, p0, j);
                float f1 = __shfl_sync(0xffffffffu, p1, j);
                float a  = lane < 16 ? f0 : f1;
                float2 v = xp2[(long long)ss * 32 + lane];
                ax = fmaf(v.x, a, ax); ay = fmaf(v.y, a, ay);
            }
        }
        int rem = deg - base;
        if (rem) {
            int s = 0; float p0 = 0.f, p1 = 0.f;
            if (lane < rem) {
                s = g_src[start + base + lane];
                float2 as = g_as[s];
                float e0 = as.x + ad.x; e0 = e0 > 0.f ? e0 : 0.2f * e0;
                float e1 = as.y + ad.y; e1 = e1 > 0.f ? e1 : 0.2f * e1;
                p0 = expf(e0 - m0); p1 = expf(e1 - m1);
            }
            d0 += p0; d1 += p1;
            for (int j = 0; j < rem; j++) {
                int   ss = __shfl_sync(0xffffffffu, s,  j);
                float f0 = __shfl_sync(0xffffffffu, p0, j);
                float f1 = __shfl_sync(0xffffffffu, p1, j);
                float a  = lane < 16 ? f0 : f1;
                float2 v = xp2[(long long)ss * 32 + lane];
                ax = fmaf(v.x, a, ax); ay = fmaf(v.y, a, ay);
            }
        }
    }
#pragma unroll
    for (int o = 16; o; o >>= 1) {
        d0 += __shfl_xor_sync(0xffffffffu, d0, o);
        d1 += __shfl_xor_sync(0xffffffffu, d1, o);
    }
    float r = 1.f / (lane < 16 ? d0 : d1);
    float2 bb = ((const float2*)b2)[lane];
    float v0 = fmaf(ax, r, bb.x), v1 = fmaf(ay, r, bb.y);
    float m = fmaxf(v0, v1);
#pragma unroll
    for (int o = 16; o; o >>= 1) m = fmaxf(m, __shfl_xor_sync(0xffffffffu, m, o));
    float sm = expf(v0 - m) + expf(v1 - m);
#pragma unroll
    for (int o = 16; o; o >>= 1) sm += __shfl_xor_sync(0xffffffffu, sm, o);
    float lse = m + logf(sm);
    ((float2*)out)[(long long)node * 32 + lane] = make_float2(v0 - lse, v1 - lse);
}

// ---------------------------------------------------------------------------
extern "C" void kernel_launch(void* const* d_in, const int* in_sizes, int n_in,
                              void* d_out, int out_size) {
    const float* x   = (const float*)d_in[0];
    const void*  ei  = d_in[1];
    const float* W1  = (const float*)d_in[2];
    const float* a1s = (const float*)d_in[3];
    const float* a1d = (const float*)d_in[4];
    const float* b1  = (const float*)d_in[5];
    const float* W2  = (const float*)d_in[6];
    const float* a2s = (const float*)d_in[7];
    const float* a2d = (const float*)d_in[8];
    const float* b2  = (const float*)d_in[9];
    float* out = (float*)d_out;

    const int n  = in_sizes[0] / 128;          // 50000
    const int E  = in_sizes[1] / 2;            // 800000
    const int Et = E + n;
    const int nb = (n + 1023) / 1024;

    float *xp1, *h, *xp2;
    cudaGetSymbolAddress((void**)&xp1, g_xp1);
    cudaGetSymbolAddress((void**)&h,   g_h);
    cudaGetSymbolAddress((void**)&xp2, g_xp2);

    // one-time host-side resources (no device memory involved)
    static cudaStream_t s_csr = 0;
    static cudaEvent_t  ev_fork = 0, ev_join = 0;
    if (s_csr == 0) {
        cudaStreamCreateWithFlags(&s_csr, cudaStreamNonBlocking);
        cudaEventCreateWithFlags(&ev_fork, cudaEventDisableTiming);
        cudaEventCreateWithFlags(&ev_join, cudaEventDisableTiming);
    }

    const int B = 256;
    const int nwB = (n * 32 + B - 1) / B;

    bool fork = (s_csr != 0 && ev_fork != 0 && ev_join != 0);
    cudaStream_t sc = fork ? s_csr : 0;

    if (fork) {
        cudaEventRecord(ev_fork, 0);             // fork from capture-origin stream
        cudaStreamWaitEvent(sc, ev_fork, 0);
    }

    // ---- CSR build (side stream) ----
    init_k     <<<(n + B - 1) / B, B, 0, sc>>>((const unsigned*)ei, n);
    hist_k     <<<(Et + B - 1) / B, B, 0, sc>>>(ei, E, n);
    scan_bsum_k<<<nb, 256, 0, sc>>>(n);
    scan_top_k <<<1, 64, 0, sc>>>(nb);
    scan_out_k <<<nb, 256, 0, sc>>>(n);
    scatter_k  <<<(Et + B - 1) / B, B, 0, sc>>>(ei, E, n);

    // ---- layer-1 GEMM (+attn dots), concurrent with CSR build ----
    gemm_attn_k<128, 64><<<(n + 63) / 64, 256>>>(x, W1, xp1, a1s, a1d, n);

    if (fork) {
        cudaEventRecord(ev_join, sc);            // join before aggregation
        cudaStreamWaitEvent(0, ev_join, 0);
    }

    agg1_k<<<nwB, B>>>(xp1, b1, h, n);

    // ---- layer 2 ----
    gemm_attn_k<64, 128><<<(n + 127) / 128, 256>>>(h, W2, xp2, a2s, a2d, n);
    agg2_k<<<nwB, B>>>(xp2, b2, out, n);
}

// round 6
// speedup vs baseline: 3.1327x; 1.0255x over previous
#include <cuda_runtime.h>
#include <cuda_fp16.h>
#include <math.h>

// ---------------------------------------------------------------------------
// 2-layer GAT forward, CSR-based, forked graph capture.
//   side stream: CSR build (init+detect/hist/scan x3/scatter)
//   main stream: gemm1 (+fused attn dots, fp16 xp output)
//   join -> agg1 (half gather, fp32 accum) -> gemm2(+attn) -> agg2
// ---------------------------------------------------------------------------

#define NN 50000
#define EE 800000
#define ET (EE + NN)
#define NB ((NN + 1023) / 1024)

typedef unsigned long long ull;

// -------- scratch (device globals; no allocation allowed) -------------------
__device__ __half g_xp1h[NN * 128];   // fp16 xp1 (only consumer: agg1 gather)
__device__ float  g_h   [NN * 128];   // fp32 layer-1 output (gemm2 input)
__device__ __half g_xp2h[NN * 64];    // fp16 xp2 (only consumer: agg2 gather)
__device__ float2 g_as  [NN];
__device__ float2 g_ad  [NN];
__device__ int    g_deg[NN];
__device__ int    g_row[NN];
__device__ int    g_cur[NN];
__device__ int    g_src[ET];
__device__ int    g_bsum[NB];
__device__ int    g_boff[NB];
__device__ int    g_is32 = 0;   // only ever set to 1 (idempotent across replays)

// -------- packed f32x2 helpers ----------------------------------------------
__device__ __forceinline__ ull pack2(float lo, float hi) {
    ull r; asm("mov.b64 %0, {%1, %2};" : "=l"(r) : "f"(lo), "f"(hi)); return r;
}
__device__ __forceinline__ void unpack2(ull v, float& lo, float& hi) {
    asm("mov.b64 {%0, %1}, %2;" : "=f"(lo), "=f"(hi) : "l"(v));
}
__device__ __forceinline__ ull fma2(ull a, ull b, ull c) {
    ull d; asm("fma.rn.f32x2 %0, %1, %2, %3;" : "=l"(d) : "l"(a), "l"(b), "l"(c));
    return d;
}

// -------- edge decode --------------------------------------------------------
__device__ __forceinline__ void load_edge(const void* ei, int E, int e,
                                          int& s, int& d) {
    if (e >= E) { s = d = e - E; return; }            // self loop
    if (g_is32) {
        const int* p = (const int*)ei;
        s = p[e]; d = p[E + e];
    } else {
        const long long* p = (const long long*)ei;
        s = (int)p[e]; d = (int)p[E + e];
    }
}

// -------- CSR build ----------------------------------------------------------
// int32 layout => odd 32-bit words are node ids (some nonzero);
// int64 layout => odd words are high halves of values < 2^31 => all zero.
__global__ void init_k(const unsigned* w, int n) {
    int i = blockIdx.x * blockDim.x + threadIdx.x;
    if (i < n) g_deg[i] = 0;
    if (i < 4096 && w[2 * i + 1] != 0u) g_is32 = 1;
}
__global__ void hist_k(const void* ei, int E, int n) {
    int e = blockIdx.x * blockDim.x + threadIdx.x;
    if (e >= E + n) return;
    int d;
    if (e >= E) d = e - E;
    else if (g_is32) d = ((const int*)ei)[E + e];
    else             d = (int)((const long long*)ei)[E + e];
    atomicAdd(&g_deg[d], 1);
}
__global__ void scan_bsum_k(int n) {
    __shared__ int wsum[8];
    int b = blockIdx.x, t = threadIdx.x;
    int base = b * 1024 + t * 4;
    int s = 0;
#pragma unroll
    for (int j = 0; j < 4; j++) {
        int i = base + j;
        if (i < n) s += g_deg[i];
    }
    int lane = t & 31, w = t >> 5;
#pragma unroll
    for (int o = 16; o; o >>= 1) s += __shfl_xor_sync(0xffffffffu, s, o);
    if (lane == 0) wsum[w] = s;
    __syncthreads();
    if (t == 0) {
        int tot = 0;
#pragma unroll
        for (int j = 0; j < 8; j++) tot += wsum[j];
        g_bsum[b] = tot;
    }
}
__global__ void scan_top_k(int nb) {
    __shared__ int w0tot;
    int t = threadIdx.x, lane = t & 31, w = t >> 5;
    int v = (t < nb) ? g_bsum[t] : 0;
    int inc = v;
#pragma unroll
    for (int o = 1; o < 32; o <<= 1) {
        int x = __shfl_up_sync(0xffffffffu, inc, o);
        if (lane >= o) inc += x;
    }
    if (w == 0 && lane == 31) w0tot = inc;
    __syncthreads();
    if (w == 1) inc += w0tot;
    if (t < nb) g_boff[t] = inc - v;
}
__global__ void scan_out_k(int n) {
    __shared__ int wsum[8], woff[8];
    int b = blockIdx.x, t = threadIdx.x;
    int lane = t & 31, w = t >> 5;
    int base = b * 1024 + t * 4;
    int v[4];
#pragma unroll
    for (int j = 0; j < 4; j++) {
        int i = base + j;
        v[j] = (i < n) ? g_deg[i] : 0;
    }
    int s = v[0] + v[1] + v[2] + v[3];
    int inc = s;
#pragma unroll
    for (int o = 1; o < 32; o <<= 1) {
        int x = __shfl_up_sync(0xffffffffu, inc, o);
        if (lane >= o) inc += x;
    }
    if (lane == 31) wsum[w] = inc;
    __syncthreads();
    if (w == 0) {
        int x = (lane < 8) ? wsum[lane] : 0;
        int i8 = x;
#pragma unroll
        for (int o = 1; o < 8; o <<= 1) {
            int y = __shfl_up_sync(0xffffffffu, i8, o);
            if (lane >= o) i8 += y;
        }
        if (lane < 8) woff[lane] = i8 - x;
    }
    __syncthreads();
    int off = g_boff[b] + woff[w] + (inc - s);
#pragma unroll
    for (int j = 0; j < 4; j++) {
        int i = base + j;
        if (i < n) { g_row[i] = off; g_cur[i] = off; }
        off += v[j];
    }
}
__global__ void scatter_k(const void* ei, int E, int n) {
    int e = blockIdx.x * blockDim.x + threadIdx.x;
    if (e >= E + n) return;
    int s, d; load_edge(ei, E, e, s, d);
    int pos = atomicAdd(&g_cur[d], 1);
    g_src[pos] = s;
}

// -------- f32x2 GEMM + fused attn dots; fp16 output -------------------------
// Yh[n,C] (half) = X[n,128] @ W[128,C];  g_as/g_ad = per-head dots (fp32)
template <int C, int BM>
__global__ void gemm_attn_k(const float* __restrict__ X, const float* __restrict__ W,
                            __half* __restrict__ Yh, const float* __restrict__ As,
                            const float* __restrict__ Ad, int n) {
    constexpr int K = 128, BK = 16, TM = 8, TN = 4;
    constexpr int TCOLS = C / TN;
    constexpr int NT    = (BM / TM) * TCOLS;    // 256
    constexpr int GW    = (C / 2) / TN;         // lanes per head group
    __shared__ __align__(16) float Xs[BK][BM];
    __shared__ __align__(16) float Ws[BK][C];
    const int tid = threadIdx.x;
    const int tc = tid % TCOLS, tr = tid / TCOLS;
    const int row0 = blockIdx.x * BM;
    ull acc2[TM / 2][TN];
#pragma unroll
    for (int ip = 0; ip < TM / 2; ip++)
#pragma unroll
        for (int j = 0; j < TN; j++) acc2[ip][j] = pack2(0.f, 0.f);

    for (int kt = 0; kt < K; kt += BK) {
#pragma unroll
        for (int idx = tid; idx < BM * BK / 4; idx += NT) {
            int m = idx / (BK / 4), q = idx % (BK / 4);
            float4 v = make_float4(0.f, 0.f, 0.f, 0.f);
            if (row0 + m < n)
                v = *(const float4*)&X[(long long)(row0 + m) * K + kt + q * 4];
            Xs[q * 4 + 0][m] = v.x; Xs[q * 4 + 1][m] = v.y;
            Xs[q * 4 + 2][m] = v.z; Xs[q * 4 + 3][m] = v.w;
        }
#pragma unroll
        for (int idx = tid; idx < BK * C / 4; idx += NT) {
            int k = idx / (C / 4), q = idx % (C / 4);
            *(float4*)&Ws[k][q * 4] = *(const float4*)&W[(kt + k) * C + q * 4];
        }
        __syncthreads();
#pragma unroll
        for (int k = 0; k < BK; k++) {
            ull x2[TM / 2];
#pragma unroll
            for (int ip = 0; ip < TM / 2; ip++)
                x2[ip] = *(const ull*)&Xs[k][tr * TM + 2 * ip];
            float4 w = *(const float4*)&Ws[k][tc * TN];
            ull wd[TN] = {pack2(w.x, w.x), pack2(w.y, w.y),
                          pack2(w.z, w.z), pack2(w.w, w.w)};
#pragma unroll
            for (int ip = 0; ip < TM / 2; ip++)
#pragma unroll
                for (int j = 0; j < TN; j++)
                    acc2[ip][j] = fma2(x2[ip], wd[j], acc2[ip][j]);
        }
        __syncthreads();
    }
    float accf[TM][TN];
#pragma unroll
    for (int ip = 0; ip < TM / 2; ip++)
#pragma unroll
        for (int j = 0; j < TN; j++)
            unpack2(acc2[ip][j], accf[2 * ip][j], accf[2 * ip + 1][j]);
    // fp16 store: 4 channels -> 2 half2 = uint2 (8B aligned)
#pragma unroll
    for (int i = 0; i < TM; i++) {
        int r = row0 + tr * TM + i;
        if (r < n) {
            __half2 h0 = __floats2half2_rn(accf[i][0], accf[i][1]);
            __half2 h1 = __floats2half2_rn(accf[i][2], accf[i][3]);
            uint2 u; u.x = *(unsigned*)&h0; u.y = *(unsigned*)&h1;
            *(uint2*)&Yh[(long long)r * C + tc * TN] = u;
        }
    }
    // fused attn dots (fp32 accumulators)
    float4 av = ((const float4*)As)[tc];
    float4 dv = ((const float4*)Ad)[tc];
    float sdot[TM], ddot[TM];
#pragma unroll
    for (int i = 0; i < TM; i++) {
        sdot[i] = accf[i][0] * av.x + accf[i][1] * av.y +
                  accf[i][2] * av.z + accf[i][3] * av.w;
        ddot[i] = accf[i][0] * dv.x + accf[i][1] * dv.y +
                  accf[i][2] * dv.z + accf[i][3] * dv.w;
#pragma unroll
        for (int o = GW / 2; o; o >>= 1) {
            sdot[i] += __shfl_xor_sync(0xffffffffu, sdot[i], o);
            ddot[i] += __shfl_xor_sync(0xffffffffu, ddot[i], o);
        }
    }
    if ((tc & (GW - 1)) == 0) {
        int h = (tc / GW) & 1;
#pragma unroll
        for (int i = 0; i < TM; i++) {
            int r = row0 + tr * TM + i;
            if (r < n) {
                ((float*)g_as)[r * 2 + h] = sdot[i];
                ((float*)g_ad)[r * 2 + h] = ddot[i];
            }
        }
    }
}

// -------- fused softmax+agg, layer 1: half gather, fp32 accum ---------------
__global__ void agg1_k(const __half* __restrict__ xph, const float* __restrict__ b1,
                       float* __restrict__ h, int n) {
    int g = blockIdx.x * blockDim.x + threadIdx.x;
    int node = g >> 5, lane = g & 31;
    if (node >= n) return;
    int start = g_row[node], deg = g_deg[node];
    float2 ad = g_ad[node];
    float4 acc = make_float4(0.f, 0.f, 0.f, 0.f);
    float d0 = 0.f, d1 = 0.f;
    const uint2* xp = (const uint2*)xph;   // 4 halves per lane (channels lane*4..+3)

    if (deg <= 32) {
        int s = 0; float e0 = -1e30f, e1 = -1e30f;
        if (lane < deg) {
            s = g_src[start + lane];
            float2 as = g_as[s];
            e0 = as.x + ad.x; e0 = e0 > 0.f ? e0 : 0.2f * e0;
            e1 = as.y + ad.y; e1 = e1 > 0.f ? e1 : 0.2f * e1;
        }
        float m0 = e0, m1 = e1;
#pragma unroll
        for (int o = 16; o; o >>= 1) {
            m0 = fmaxf(m0, __shfl_xor_sync(0xffffffffu, m0, o));
            m1 = fmaxf(m1, __shfl_xor_sync(0xffffffffu, m1, o));
        }
        float p0 = 0.f, p1 = 0.f;
        if (lane < deg) { p0 = expf(e0 - m0); p1 = expf(e1 - m1); }
        d0 = p0; d1 = p1;
        for (int j = 0; j < deg; j++) {
            int   ss = __shfl_sync(0xffffffffu, s,  j);
            float f0 = __shfl_sync(0xffffffffu, p0, j);
            float f1 = __shfl_sync(0xffffffffu, p1, j);
            float a  = lane < 16 ? f0 : f1;
            uint2 u = xp[(long long)ss * 32 + lane];
            float2 va = __half22float2(*(__half2*)&u.x);
            float2 vb = __half22float2(*(__half2*)&u.y);
            acc.x = fmaf(va.x, a, acc.x); acc.y = fmaf(va.y, a, acc.y);
            acc.z = fmaf(vb.x, a, acc.z); acc.w = fmaf(vb.y, a, acc.w);
        }
    } else {
        float m0 = -1e30f, m1 = -1e30f;
        for (int i = lane; i < deg; i += 32) {
            float2 as = g_as[g_src[start + i]];
            float e0 = as.x + ad.x; e0 = e0 > 0.f ? e0 : 0.2f * e0;
            float e1 = as.y + ad.y; e1 = e1 > 0.f ? e1 : 0.2f * e1;
            m0 = fmaxf(m0, e0); m1 = fmaxf(m1, e1);
        }
#pragma unroll
        for (int o = 16; o; o >>= 1) {
            m0 = fmaxf(m0, __shfl_xor_sync(0xffffffffu, m0, o));
            m1 = fmaxf(m1, __shfl_xor_sync(0xffffffffu, m1, o));
        }
        int base = 0;
        for (; base + 32 <= deg; base += 32) {
            int s = g_src[start + base + lane];
            float2 as = g_as[s];
            float e0 = as.x + ad.x; e0 = e0 > 0.f ? e0 : 0.2f * e0;
            float e1 = as.y + ad.y; e1 = e1 > 0.f ? e1 : 0.2f * e1;
            float p0 = expf(e0 - m0), p1 = expf(e1 - m1);
            d0 += p0; d1 += p1;
#pragma unroll 4
            for (int j = 0; j < 32; j++) {
                int   ss = __shfl_sync(0xffffffffu, s,  j);
                float f0 = __shfl_sync(0xffffffffu, p0, j);
                float f1 = __shfl_sync(0xffffffffu, p1, j);
                float a  = lane < 16 ? f0 : f1;
                uint2 u = xp[(long long)ss * 32 + lane];
                float2 va = __half22float2(*(__half2*)&u.x);
                float2 vb = __half22float2(*(__half2*)&u.y);
                acc.x = fmaf(va.x, a, acc.x); acc.y = fmaf(va.y, a, acc.y);
                acc.z = fmaf(vb.x, a, acc.z); acc.w = fmaf(vb.y, a, acc.w);
            }
        }
        int rem = deg - base;
        if (rem) {
            int s = 0; float p0 = 0.f, p1 = 0.f;
            if (lane < rem) {
                s = g_src[start + base + lane];
                float2 as = g_as[s];
                float e0 = as.x + ad.x; e0 = e0 > 0.f ? e0 : 0.2f * e0;
                float e1 = as.y + ad.y; e1 = e1 > 0.f ? e1 : 0.2f * e1;
                p0 = expf(e0 - m0); p1 = expf(e1 - m1);
            }
            d0 += p0; d1 += p1;
            for (int j = 0; j < rem; j++) {
                int   ss = __shfl_sync(0xffffffffu, s,  j);
                float f0 = __shfl_sync(0xffffffffu, p0, j);
                float f1 = __shfl_sync(0xffffffffu, p1, j);
                float a  = lane < 16 ? f0 : f1;
                uint2 u = xp[(long long)ss * 32 + lane];
                float2 va = __half22float2(*(__half2*)&u.x);
                float2 vb = __half22float2(*(__half2*)&u.y);
                acc.x = fmaf(va.x, a, acc.x); acc.y = fmaf(va.y, a, acc.y);
                acc.z = fmaf(vb.x, a, acc.z); acc.w = fmaf(vb.y, a, acc.w);
            }
        }
    }
#pragma unroll
    for (int o = 16; o; o >>= 1) {
        d0 += __shfl_xor_sync(0xffffffffu, d0, o);
        d1 += __shfl_xor_sync(0xffffffffu, d1, o);
    }
    float r = 1.f / (lane < 16 ? d0 : d1);
    float4 bb = ((const float4*)b1)[lane];
    acc.x = fmaf(acc.x, r, bb.x); acc.y = fmaf(acc.y, r, bb.y);
    acc.z = fmaf(acc.z, r, bb.z); acc.w = fmaf(acc.w, r, bb.w);
    acc.x = acc.x > 0.f ? acc.x : expm1f(acc.x);
    acc.y = acc.y > 0.f ? acc.y : expm1f(acc.y);
    acc.z = acc.z > 0.f ? acc.z : expm1f(acc.z);
    acc.w = acc.w > 0.f ? acc.w : expm1f(acc.w);
    ((float4*)h)[(long long)node * 32 + lane] = acc;
}

// -------- fused softmax+agg, layer 2 (+bias, log_softmax); half gather ------
__global__ void agg2_k(const __half* __restrict__ xph, const float* __restrict__ b2,
                       float* __restrict__ out, int n) {
    int g = blockIdx.x * blockDim.x + threadIdx.x;
    int node = g >> 5, lane = g & 31;
    if (node >= n) return;
    int start = g_row[node], deg = g_deg[node];
    float2 ad = g_ad[node];
    float ax = 0.f, ay = 0.f, d0 = 0.f, d1 = 0.f;
    const unsigned* xp = (const unsigned*)xph;   // half2 per lane (channels lane*2, +1)

    if (deg <= 32) {
        int s = 0; float e0 = -1e30f, e1 = -1e30f;
        if (lane < deg) {
            s = g_src[start + lane];
            float2 as = g_as[s];
            e0 = as.x + ad.x; e0 = e0 > 0.f ? e0 : 0.2f * e0;
            e1 = as.y + ad.y; e1 = e1 > 0.f ? e1 : 0.2f * e1;
        }
        float m0 = e0, m1 = e1;
#pragma unroll
        for (int o = 16; o; o >>= 1) {
            m0 = fmaxf(m0, __shfl_xor_sync(0xffffffffu, m0, o));
            m1 = fmaxf(m1, __shfl_xor_sync(0xffffffffu, m1, o));
        }
        float p0 = 0.f, p1 = 0.f;
        if (lane < deg) { p0 = expf(e0 - m0); p1 = expf(e1 - m1); }
        d0 = p0; d1 = p1;
        for (int j = 0; j < deg; j++) {
            int   ss = __shfl_sync(0xffffffffu, s,  j);
            float f0 = __shfl_sync(0xffffffffu, p0, j);
            float f1 = __shfl_sync(0xffffffffu, p1, j);
            float a  = lane < 16 ? f0 : f1;
            unsigned u = xp[(long long)ss * 32 + lane];
            float2 v = __half22float2(*(__half2*)&u);
            ax = fmaf(v.x, a, ax); ay = fmaf(v.y, a, ay);
        }
    } else {
        float m0 = -1e30f, m1 = -1e30f;
        for (int i = lane; i < deg; i += 32) {
            float2 as = g_as[g_src[start + i]];
            float e0 = as.x + ad.x; e0 = e0 > 0.f ? e0 : 0.2f * e0;
            float e1 = as.y + ad.y; e1 = e1 > 0.f ? e1 : 0.2f * e1;
            m0 = fmaxf(m0, e0); m1 = fmaxf(m1, e1);
        }
#pragma unroll
        for (int o = 16; o; o >>= 1) {
            m0 = fmaxf(m0, __shfl_xor_sync(0xffffffffu, m0, o));
            m1 = fmaxf(m1, __shfl_xor_sync(0xffffffffu, m1, o));
        }
        int base = 0;
        for (; base + 32 <= deg; base += 32) {
            int s = g_src[start + base + lane];
            float2 as = g_as[s];
            float e0 = as.x + ad.x; e0 = e0 > 0.f ? e0 : 0.2f * e0;
            float e1 = as.y + ad.y; e1 = e1 > 0.f ? e1 : 0.2f * e1;
            float p0 = expf(e0 - m0), p1 = expf(e1 - m1);
            d0 += p0; d1 += p1;
#pragma unroll 4
            for (int j = 0; j < 32; j++) {
                int   ss = __shfl_sync(0xffffffffu, s,  j);
                float f0 = __shfl_sync(0xffffffffu, p0, j);
                float f1 = __shfl_sync(0xffffffffu, p1, j);
                float a  = lane < 16 ? f0 : f1;
                unsigned u = xp[(long long)ss * 32 + lane];
                float2 v = __half22float2(*(__half2*)&u);
                ax = fmaf(v.x, a, ax); ay = fmaf(v.y, a, ay);
            }
        }
        int rem = deg - base;
        if (rem) {
            int s = 0; float p0 = 0.f, p1 = 0.f;
            if (lane < rem) {
                s = g_src[start + base + lane];
                float2 as = g_as[s];
                float e0 = as.x + ad.x; e0 = e0 > 0.f ? e0 : 0.2f * e0;
                float e1 = as.y + ad.y; e1 = e1 > 0.f ? e1 : 0.2f * e1;
                p0 = expf(e0 - m0); p1 = expf(e1 - m1);
            }
            d0 += p0; d1 += p1;
            for (int j = 0; j < rem; j++) {
                int   ss = __shfl_sync(0xffffffffu, s,  j);
                float f0 = __shfl_sync(0xffffffffu, p0, j);
                float f1 = __shfl_sync(0xffffffffu, p1, j);
                float a  = lane < 16 ? f0 : f1;
                unsigned u = xp[(long long)ss * 32 + lane];
                float2 v = __half22float2(*(__half2*)&u);
                ax = fmaf(v.x, a, ax); ay = fmaf(v.y, a, ay);
            }
        }
    }
#pragma unroll
    for (int o = 16; o; o >>= 1) {
        d0 += __shfl_xor_sync(0xffffffffu, d0, o);
        d1 += __shfl_xor_sync(0xffffffffu, d1, o);
    }
    float r = 1.f / (lane < 16 ? d0 : d1);
    float2 bb = ((const float2*)b2)[lane];
    float v0 = fmaf(ax, r, bb.x), v1 = fmaf(ay, r, bb.y);
    float m = fmaxf(v0, v1);
#pragma unroll
    for (int o = 16; o; o >>= 1) m = fmaxf(m, __shfl_xor_sync(0xffffffffu, m, o));
    float sm = expf(v0 - m) + expf(v1 - m);
#pragma unroll
    for (int o = 16; o; o >>= 1) sm += __shfl_xor_sync(0xffffffffu, sm, o);
    float lse = m + logf(sm);
    ((float2*)out)[(long long)node * 32 + lane] = make_float2(v0 - lse, v1 - lse);
}

// ---------------------------------------------------------------------------
extern "C" void kernel_launch(void* const* d_in, const int* in_sizes, int n_in,
                              void* d_out, int out_size) {
    const float* x   = (const float*)d_in[0];
    const void*  ei  = d_in[1];
    const float* W1  = (const float*)d_in[2];
    const float* a1s = (const float*)d_in[3];
    const float* a1d = (const float*)d_in[4];
    const float* b1  = (const float*)d_in[5];
    const float* W2  = (const float*)d_in[6];
    const float* a2s = (const float*)d_in[7];
    const float* a2d = (const float*)d_in[8];
    const float* b2  = (const float*)d_in[9];
    float* out = (float*)d_out;

    const int n  = in_sizes[0] / 128;          // 50000
    const int E  = in_sizes[1] / 2;            // 800000
    const int Et = E + n;
    const int nb = (n + 1023) / 1024;

    __half *xp1h, *xp2h; float* h;
    cudaGetSymbolAddress((void**)&xp1h, g_xp1h);
    cudaGetSymbolAddress((void**)&h,    g_h);
    cudaGetSymbolAddress((void**)&xp2h, g_xp2h);

    // one-time host-side resources (no device memory involved)
    static cudaStream_t s_csr = 0;
    static cudaEvent_t  ev_fork = 0, ev_join = 0;
    if (s_csr == 0) {
        cudaStreamCreateWithFlags(&s_csr, cudaStreamNonBlocking);
        cudaEventCreateWithFlags(&ev_fork, cudaEventDisableTiming);
        cudaEventCreateWithFlags(&ev_join, cudaEventDisableTiming);
    }

    const int B = 256;
    const int nwB = (n * 32 + B - 1) / B;

    bool fork = (s_csr != 0 && ev_fork != 0 && ev_join != 0);
    cudaStream_t sc = fork ? s_csr : 0;

    if (fork) {
        cudaEventRecord(ev_fork, 0);
        cudaStreamWaitEvent(sc, ev_fork, 0);
    }

    // ---- CSR build (side stream) ----
    init_k     <<<(n + B - 1) / B, B, 0, sc>>>((const unsigned*)ei, n);
    hist_k     <<<(Et + B - 1) / B, B, 0, sc>>>(ei, E, n);
    scan_bsum_k<<<nb, 256, 0, sc>>>(n);
    scan_top_k <<<1, 64, 0, sc>>>(nb);
    scan_out_k <<<nb, 256, 0, sc>>>(n);
    scatter_k  <<<(Et + B - 1) / B, B, 0, sc>>>(ei, E, n);

    // ---- layer-1 GEMM (+attn dots), concurrent with CSR build ----
    gemm_attn_k<128, 64><<<(n + 63) / 64, 256>>>(x, W1, xp1h, a1s, a1d, n);

    if (fork) {
        cudaEventRecord(ev_join, sc);
        cudaStreamWaitEvent(0, ev_join, 0);
    }

    agg1_k<<<nwB, B>>>(xp1h, b1, h, n);

    // ---- layer 2 ----
    gemm_attn_k<64, 128><<<(n + 127) / 128, 256>>>(h, W2, xp2h, a2s, a2d, n);
    agg2_k<<<nwB, B>>>(xp2h, b2, out, n);
}